// round 15
// baseline (speedup 1.0000x reference)
#include <cuda_runtime.h>
#include <cuda_bf16.h>
#include <math.h>
#include <stdint.h>
#include <string.h>

#define BB 4
#define TT 1024
#define CC 1024
#define HH 16
#define NN 64
#define MM (BB*TT)   // 4096 rows

typedef __nv_bfloat16 bf16;

// ---------------------------------------------------------------------------
// Scratch (static device memory)
// ---------------------------------------------------------------------------
struct Scratch {
    float xx   [MM*CC];
    float r    [MM*CC];
    float k    [MM*CC];
    float v    [MM*CC];
    float g    [MM*CC];
    float w    [MM*CC];
    float kk   [MM*CC];
    float asig [MM*CC];
    float ma   [MM*CC];
    float mk2  [MM*CC];
    float kf   [MM*CC];
    float dd   [MM*CC];
    float av   [MM*CC];
    float bv   [MM*CC];
    float y    [MM*CC];
    // bf16 hi/lo activations
    bf16 xmixh[MM*CC], xmixl[MM*CC];
    bf16 mixinh[MM*128], mixinl[MM*128];
    bf16 xrgh[MM*CC], xrgl[MM*CC];
    bf16 xwah[MM*CC], xwal[MM*CC];
    bf16 xkh [MM*CC], xkl [MM*CC];
    bf16 xvh [MM*CC], xvl [MM*CC];
    bf16 zh  [MM*CC], zl  [MM*CC];
    bf16 g1h [MM*128], g1l [MM*128];
    bf16 loraAh[MM*160], loraAl[MM*160];
    // bf16 hi/lo weights
    bf16 wrh[CC*CC], wrl[CC*CC];
    bf16 wkh[CC*CC], wkl[CC*CC];
    bf16 wvh[CC*CC], wvl[CC*CC];
    bf16 woh[CC*CC], wol[CC*CC];
    bf16 gw2Th[CC*128], gw2Tl[CC*128];
    bf16 mw1Th[128*1024], mw1Tl[128*1024];
    bf16 w2Th[4096*32],  w2Tl[4096*32];
    bf16 gw1Th[128*1024], gw1Tl[128*1024];
    bf16 waTh [128*1024], waTl [128*1024];
    bf16 kTh  [64*1024],  kTl  [64*1024];
    bf16 bigBh[5120*160], bigBl[5120*160];
};
__device__ Scratch g_s;

// ---------------------------------------------------------------------------
// Packed f32x2 helpers
// ---------------------------------------------------------------------------
__device__ __forceinline__ unsigned long long dup2(float x) {
    unsigned long long r;
    asm("mov.b64 %0, {%1, %1};" : "=l"(r) : "f"(x));
    return r;
}
__device__ __forceinline__ void fma2(unsigned long long& acc,
                                     unsigned long long a,
                                     unsigned long long b) {
    asm("fma.rn.f32x2 %0, %1, %2, %0;" : "+l"(acc) : "l"(a), "l"(b));
}
__device__ __forceinline__ unsigned long long fma2g(unsigned long long a,
                                                    unsigned long long b,
                                                    unsigned long long c) {
    unsigned long long d;
    asm("fma.rn.f32x2 %0, %1, %2, %3;" : "=l"(d) : "l"(a), "l"(b), "l"(c));
    return d;
}
__device__ __forceinline__ unsigned long long mul2(unsigned long long a,
                                                   unsigned long long b) {
    unsigned long long d;
    asm("mul.rn.f32x2 %0, %1, %2;" : "=l"(d) : "l"(a), "l"(b));
    return d;
}
__device__ __forceinline__ float2 unpack2(unsigned long long v) {
    float2 f;
    asm("mov.b64 {%0, %1}, %2;" : "=f"(f.x), "=f"(f.y) : "l"(v));
    return f;
}
__device__ __forceinline__ float hadd4(unsigned long long a,
                                       unsigned long long b) {
    float2 f = unpack2(a), g = unpack2(b);
    return (f.x + f.y) + (g.x + g.y);
}
__device__ __forceinline__ uint32_t smem_u32(const void* p) {
    uint32_t a;
    asm("{ .reg .u64 t; cvta.to.shared.u64 t, %1; cvt.u32.u64 %0, t; }"
        : "=r"(a) : "l"(p));
    return a;
}

// cp.async helpers
__device__ __forceinline__ void cp_async16(uint32_t saddr, const void* gptr) {
    asm volatile("cp.async.cg.shared.global [%0], [%1], 16;"
        :: "r"(saddr), "l"(gptr) : "memory");
}
#define CP_COMMIT() asm volatile("cp.async.commit_group;" ::: "memory")
#define CP_WAIT0()  asm volatile("cp.async.wait_group 0;" ::: "memory")
#define CP_WAIT2()  asm volatile("cp.async.wait_group 2;" ::: "memory")

// hi/lo splits
__device__ __forceinline__ void split4(float4 f, uint2& h, uint2& l) {
    __nv_bfloat162 h01 = __floats2bfloat162_rn(f.x, f.y);
    __nv_bfloat162 h23 = __floats2bfloat162_rn(f.z, f.w);
    float lx = f.x - __bfloat162float(h01.x);
    float ly = f.y - __bfloat162float(h01.y);
    float lz = f.z - __bfloat162float(h23.x);
    float lw = f.w - __bfloat162float(h23.y);
    __nv_bfloat162 l01 = __floats2bfloat162_rn(lx, ly);
    __nv_bfloat162 l23 = __floats2bfloat162_rn(lz, lw);
    memcpy(&h.x, &h01, 4); memcpy(&h.y, &h23, 4);
    memcpy(&l.x, &l01, 4); memcpy(&l.y, &l23, 4);
}
__device__ __forceinline__ void split2(float a, float b,
                                       uint32_t& h, uint32_t& l) {
    __nv_bfloat162 hh = __floats2bfloat162_rn(a, b);
    float la = a - __bfloat162float(hh.x);
    float lb = b - __bfloat162float(hh.y);
    __nv_bfloat162 ll = __floats2bfloat162_rn(la, lb);
    memcpy(&h, &hh, 4); memcpy(&l, &ll, 4);
}
__device__ __forceinline__ void splitf(float v, bf16& h, bf16& l) {
    h = __float2bfloat16_rn(v);
    l = __float2bfloat16_rn(v - __bfloat162float(h));
}

// ---------------------------------------------------------------------------
// mma.sync / ldmatrix helpers
// ---------------------------------------------------------------------------
__device__ __forceinline__ void ldsm4(uint32_t* r, uint32_t addr) {
    asm volatile("ldmatrix.sync.aligned.m8n8.x4.shared.b16 {%0,%1,%2,%3}, [%4];"
        : "=r"(r[0]), "=r"(r[1]), "=r"(r[2]), "=r"(r[3]) : "r"(addr));
}
__device__ __forceinline__ void mma_bf16(float* c, const uint32_t* a,
                                         const uint32_t* b) {
    asm volatile("mma.sync.aligned.m16n8k16.row.col.f32.bf16.bf16.f32 "
        "{%0,%1,%2,%3}, {%4,%5,%6,%7}, {%8,%9}, {%0,%1,%2,%3};"
        : "+f"(c[0]), "+f"(c[1]), "+f"(c[2]), "+f"(c[3])
        : "r"(a[0]), "r"(a[1]), "r"(a[2]), "r"(a[3]), "r"(b[0]), "r"(b[1]));
}

// ---------------------------------------------------------------------------
// mma128_body: C[128,128] tile of (Ah+Al)[M,K] @ (Bh+Bl)[1024,K]^T
// cp.async double-buffered, chunk 32. Shared by gemm_mma2 / gemm_rkv.
// ---------------------------------------------------------------------------
#define MMA_SMEM 81920

__device__ __forceinline__ void mma128_body(
    const bf16* __restrict__ Ah, const bf16* __restrict__ Al,
    const bf16* __restrict__ Bh, const bf16* __restrict__ Bl,
    float* __restrict__ Cm, int K, int m0, int n0, char* sm)
{
    const uint32_t sb = smem_u32(sm);
    const int tid  = threadIdx.x;
    const int lane = tid & 31;
    const int wid  = tid >> 5;
    const int wm   = wid & 1;
    const int wn   = wid >> 1;

    const int row = tid >> 1, half = tid & 1;
    const bf16* pAh = Ah + (size_t)(m0 + row) * K + half * 16;
    const bf16* pAl = Al + (size_t)(m0 + row) * K + half * 16;
    const bf16* pBh = Bh + (size_t)(n0 + row) * K + half * 16;
    const bf16* pBl = Bl + (size_t)(n0 + row) * K + half * 16;
    const uint32_t st = (uint32_t)(row * 80 + half * 32);

    const uint32_t aLoff = (uint32_t)((lane & 15) * 80 + (lane >> 4) * 16);
    const uint32_t bLoff = (uint32_t)(((lane & 7) + ((lane >> 4) & 1) * 8) * 80
                                      + ((lane >> 3) & 1) * 16);

    float c[4][4][4];
#pragma unroll
    for (int i = 0; i < 4; i++)
#pragma unroll
        for (int j = 0; j < 4; j++)
#pragma unroll
            for (int q = 0; q < 4; q++) c[i][j][q] = 0.f;

    const int chunks = K >> 5;

    {
        uint32_t d = sb + st;
        cp_async16(d,             pAh); cp_async16(d + 16,         pAh + 8);
        cp_async16(d + 10240,     pAl); cp_async16(d + 10240 + 16, pAl + 8);
        cp_async16(d + 20480,     pBh); cp_async16(d + 20480 + 16, pBh + 8);
        cp_async16(d + 30720,     pBl); cp_async16(d + 30720 + 16, pBl + 8);
        CP_COMMIT();
        CP_WAIT0();
    }
    __syncthreads();

    for (int cidx = 0; cidx < chunks; cidx++) {
        const uint32_t bufOff = (uint32_t)((cidx & 1) * 40960);
        const bool more = (cidx + 1 < chunks);

        if (more) {
            const int ko = (cidx + 1) * 32;
            uint32_t d = sb + (uint32_t)(((cidx + 1) & 1) * 40960) + st;
            cp_async16(d,             pAh + ko); cp_async16(d + 16,         pAh + ko + 8);
            cp_async16(d + 10240,     pAl + ko); cp_async16(d + 10240 + 16, pAl + ko + 8);
            cp_async16(d + 20480,     pBh + ko); cp_async16(d + 20480 + 16, pBh + ko + 8);
            cp_async16(d + 30720,     pBl + ko); cp_async16(d + 30720 + 16, pBl + ko + 8);
            CP_COMMIT();
        }

        const uint32_t aBase = sb + bufOff + (uint32_t)(wm * 64 * 80) + aLoff;
        const uint32_t bBase = sb + bufOff + 20480u + (uint32_t)(wn * 32 * 80) + bLoff;
#pragma unroll
        for (int ks = 0; ks < 2; ks++) {
            uint32_t afh[4][4], afl[4][4];
#pragma unroll
            for (int mi = 0; mi < 4; mi++) {
                ldsm4(afh[mi], aBase + 0u     + (uint32_t)(mi * 1280 + ks * 32));
                ldsm4(afl[mi], aBase + 10240u + (uint32_t)(mi * 1280 + ks * 32));
            }
            uint32_t bfh[2][4], bfl[2][4];
#pragma unroll
            for (int np = 0; np < 2; np++) {
                ldsm4(bfh[np], bBase + 0u     + (uint32_t)(np * 1280 + ks * 32));
                ldsm4(bfl[np], bBase + 10240u + (uint32_t)(np * 1280 + ks * 32));
            }
#pragma unroll
            for (int mi = 0; mi < 4; mi++) {
#pragma unroll
                for (int ni = 0; ni < 4; ni++) {
                    const uint32_t* bh = &bfh[ni >> 1][(ni & 1) * 2];
                    const uint32_t* bl = &bfl[ni >> 1][(ni & 1) * 2];
                    mma_bf16(c[mi][ni], afh[mi], bh);
                    mma_bf16(c[mi][ni], afh[mi], bl);
                    mma_bf16(c[mi][ni], afl[mi], bh);
                }
            }
        }

        if (more) CP_WAIT0();
        __syncthreads();
    }

    const int erow = m0 + wm * 64 + (lane >> 2);
    const int ecol = n0 + wn * 32 + (lane & 3) * 2;
#pragma unroll
    for (int mi = 0; mi < 4; mi++) {
#pragma unroll
        for (int ni = 0; ni < 4; ni++) {
            size_t base0 = (size_t)(erow + mi * 16)     * 1024 + ecol + ni * 8;
            size_t base1 = (size_t)(erow + mi * 16 + 8) * 1024 + ecol + ni * 8;
            *(float2*)&Cm[base0] = make_float2(c[mi][ni][0], c[mi][ni][1]);
            *(float2*)&Cm[base1] = make_float2(c[mi][ni][2], c[mi][ni][3]);
        }
    }
}

__global__ void __launch_bounds__(256, 2)
gemm_mma2(const bf16* __restrict__ Ah, const bf16* __restrict__ Al,
          const bf16* __restrict__ Bh, const bf16* __restrict__ Bl,
          float* __restrict__ Cm, int K)
{
    extern __shared__ __align__(16) char sm[];
    mma128_body(Ah, Al, Bh, Bl, Cm, K, blockIdx.y * 128, blockIdx.x * 128, sm);
}

// batched r/k/v projections: blockIdx.z selects operand triple
__global__ void __launch_bounds__(256, 2)
gemm_rkv()
{
    extern __shared__ __align__(16) char sm[];
    const bf16 *Ah, *Al, *Bh, *Bl; float* Cm;
    switch (blockIdx.z) {
        case 0:  Ah = g_s.xrgh; Al = g_s.xrgl; Bh = g_s.wrh; Bl = g_s.wrl;
                 Cm = g_s.r; break;
        case 1:  Ah = g_s.xkh;  Al = g_s.xkl;  Bh = g_s.wkh; Bl = g_s.wkl;
                 Cm = g_s.k; break;
        default: Ah = g_s.xvh;  Al = g_s.xvl;  Bh = g_s.wvh; Bl = g_s.wvl;
                 Cm = g_s.v; break;
    }
    mma128_body(Ah, Al, Bh, Bl, Cm, 1024, blockIdx.y * 128, blockIdx.x * 128, sm);
}

// ---------------------------------------------------------------------------
// gemm_mix_mma: batched token-mix GEMM + epilogue, HMMA.
// ---------------------------------------------------------------------------
#define MIXMMA_SMEM 40960

__global__ void __launch_bounds__(256, 2)
gemm_mix_mma(const float* __restrict__ x,
             const float* __restrict__ m_rg, const float* __restrict__ m_wa,
             const float* __restrict__ m_k,  const float* __restrict__ m_v)
{
    extern __shared__ __align__(16) char sm[];
    const uint32_t sb = smem_u32(sm);

    const int tid  = threadIdx.x;
    const int lane = tid & 31;
    const int wid  = tid >> 5;
    const int wm   = wid & 1;
    const int wn   = wid >> 1;
    const int n0 = blockIdx.x * 128;
    const int m0 = blockIdx.y * 128;
    const int f  = n0 >> 10;
    const int col0 = n0 & 1023;

    const int row = tid >> 1, half = tid & 1;
    {
        const bf16* pAh = g_s.mixinh + (size_t)(m0 + row) * 128 + f * 32 + half * 16;
        const bf16* pAl = g_s.mixinl + (size_t)(m0 + row) * 128 + f * 32 + half * 16;
        const bf16* pBh = g_s.w2Th + (size_t)(n0 + row) * 32 + half * 16;
        const bf16* pBl = g_s.w2Tl + (size_t)(n0 + row) * 32 + half * 16;
        const uint32_t d = sb + (uint32_t)(row * 80 + half * 32);
        cp_async16(d,             pAh); cp_async16(d + 16,         pAh + 8);
        cp_async16(d + 10240,     pAl); cp_async16(d + 10240 + 16, pAl + 8);
        cp_async16(d + 20480,     pBh); cp_async16(d + 20480 + 16, pBh + 8);
        cp_async16(d + 30720,     pBl); cp_async16(d + 30720 + 16, pBl + 8);
        CP_COMMIT();
        CP_WAIT0();
    }
    __syncthreads();

    const uint32_t aLoff = (uint32_t)((lane & 15) * 80 + (lane >> 4) * 16);
    const uint32_t bLoff = (uint32_t)(((lane & 7) + ((lane >> 4) & 1) * 8) * 80
                                      + ((lane >> 3) & 1) * 16);

    float c[4][4][4];
#pragma unroll
    for (int i = 0; i < 4; i++)
#pragma unroll
        for (int j = 0; j < 4; j++)
#pragma unroll
            for (int q = 0; q < 4; q++) c[i][j][q] = 0.f;

    const uint32_t aBase = sb + (uint32_t)(wm * 64 * 80) + aLoff;
    const uint32_t bBase = sb + 20480u + (uint32_t)(wn * 32 * 80) + bLoff;
#pragma unroll
    for (int ks = 0; ks < 2; ks++) {
        uint32_t afh[4][4], afl[4][4];
#pragma unroll
        for (int mi = 0; mi < 4; mi++) {
            ldsm4(afh[mi], aBase + 0u     + (uint32_t)(mi * 1280 + ks * 32));
            ldsm4(afl[mi], aBase + 10240u + (uint32_t)(mi * 1280 + ks * 32));
        }
        uint32_t bfh[2][4], bfl[2][4];
#pragma unroll
        for (int np = 0; np < 2; np++) {
            ldsm4(bfh[np], bBase + 0u     + (uint32_t)(np * 1280 + ks * 32));
            ldsm4(bfl[np], bBase + 10240u + (uint32_t)(np * 1280 + ks * 32));
        }
#pragma unroll
        for (int mi = 0; mi < 4; mi++) {
#pragma unroll
            for (int ni = 0; ni < 4; ni++) {
                const uint32_t* bh = &bfh[ni >> 1][(ni & 1) * 2];
                const uint32_t* bl = &bfl[ni >> 1][(ni & 1) * 2];
                mma_bf16(c[mi][ni], afh[mi], bh);
                mma_bf16(c[mi][ni], afh[mi], bl);
                mma_bf16(c[mi][ni], afl[mi], bh);
            }
        }
    }

    const float* maa;
    bf16 *oh, *ol;
    switch (f) {
        case 0:  maa = m_rg; oh = g_s.xrgh; ol = g_s.xrgl; break;
        case 1:  maa = m_wa; oh = g_s.xwah; ol = g_s.xwal; break;
        case 2:  maa = m_k;  oh = g_s.xkh;  ol = g_s.xkl;  break;
        default: maa = m_v;  oh = g_s.xvh;  ol = g_s.xvl;  break;
    }
    const int erow = m0 + wm * 64 + (lane >> 2);
    const int ecol = col0 + wn * 32 + (lane & 3) * 2;
#pragma unroll
    for (int mi = 0; mi < 4; mi++) {
#pragma unroll
        for (int ni = 0; ni < 4; ni++) {
            const int col = ecol + ni * 8;
            const int r0 = erow + mi * 16, r1 = r0 + 8;
            const size_t off0 = (size_t)r0 * 1024 + col;
            const size_t off1 = (size_t)r1 * 1024 + col;
            float2 mv  = *(const float2*)&maa[col];
            float2 x0  = *(const float2*)&x[off0];
            float2 x1  = *(const float2*)&x[off1];
            float2 dx0 = *(const float2*)&g_s.xx[off0];
            float2 dx1 = *(const float2*)&g_s.xx[off1];
            float v0 = x0.x + dx0.x * (mv.x + c[mi][ni][0]);
            float v1 = x0.y + dx0.y * (mv.y + c[mi][ni][1]);
            float v2 = x1.x + dx1.x * (mv.x + c[mi][ni][2]);
            float v3 = x1.y + dx1.y * (mv.y + c[mi][ni][3]);
            uint32_t h0, l0, h1, l1;
            split2(v0, v1, h0, l0);
            split2(v2, v3, h1, l1);
            *(uint32_t*)&oh[off0] = h0;
            *(uint32_t*)&ol[off0] = l0;
            *(uint32_t*)&oh[off1] = h1;
            *(uint32_t*)&ol[off1] = l1;
        }
    }
}

// ---------------------------------------------------------------------------
// gemm_down: fused LoRA down-projections (block-diagonal).
// ---------------------------------------------------------------------------
__global__ void __launch_bounds__(256, 2)
gemm_down(const float* __restrict__ tdecay, const float* __restrict__ taaaaa,
          const float* __restrict__ tmisca, const float* __restrict__ tmisck)
{
    extern __shared__ __align__(16) char sm[];
    const uint32_t sb = smem_u32(sm);

    const int tid  = threadIdx.x;
    const int lane = tid & 31;
    const int wid  = tid >> 5;
    const int wm   = wid & 1;
    const int wn   = wid >> 1;
    const int n0 = blockIdx.x * 128;
    const int m0 = blockIdx.y * 128;

    const int row = tid >> 1, half = tid & 1;
    const bf16* pAh = g_s.loraAh + (size_t)(m0 + row) * 160 + half * 16;
    const bf16* pAl = g_s.loraAl + (size_t)(m0 + row) * 160 + half * 16;
    const bf16* pBh = g_s.bigBh  + (size_t)(n0 + row) * 160 + half * 16;
    const bf16* pBl = g_s.bigBl  + (size_t)(n0 + row) * 160 + half * 16;
    const uint32_t st = (uint32_t)(row * 80 + half * 32);

    const uint32_t aLoff = (uint32_t)((lane & 15) * 80 + (lane >> 4) * 16);
    const uint32_t bLoff = (uint32_t)(((lane & 7) + ((lane >> 4) & 1) * 8) * 80
                                      + ((lane >> 3) & 1) * 16);

    float c[4][4][4];
#pragma unroll
    for (int i = 0; i < 4; i++)
#pragma unroll
        for (int j = 0; j < 4; j++)
#pragma unroll
            for (int q = 0; q < 4; q++) c[i][j][q] = 0.f;

    {
        uint32_t d = sb + st;
        cp_async16(d,             pAh); cp_async16(d + 16,         pAh + 8);
        cp_async16(d + 10240,     pAl); cp_async16(d + 10240 + 16, pAl + 8);
        cp_async16(d + 20480,     pBh); cp_async16(d + 20480 + 16, pBh + 8);
        cp_async16(d + 30720,     pBl); cp_async16(d + 30720 + 16, pBl + 8);
        CP_COMMIT();
        CP_WAIT0();
    }
    __syncthreads();

    for (int cidx = 0; cidx < 5; cidx++) {
        const uint32_t bufOff = (uint32_t)((cidx & 1) * 40960);
        const bool more = (cidx + 1 < 5);

        if (more) {
            const int ko = (cidx + 1) * 32;
            uint32_t d = sb + (uint32_t)(((cidx + 1) & 1) * 40960) + st;
            cp_async16(d,             pAh + ko); cp_async16(d + 16,         pAh + ko + 8);
            cp_async16(d + 10240,     pAl + ko); cp_async16(d + 10240 + 16, pAl + ko + 8);
            cp_async16(d + 20480,     pBh + ko); cp_async16(d + 20480 + 16, pBh + ko + 8);
            cp_async16(d + 30720,     pBl + ko); cp_async16(d + 30720 + 16, pBl + ko + 8);
            CP_COMMIT();
        }

        const uint32_t aBase = sb + bufOff + (uint32_t)(wm * 64 * 80) + aLoff;
        const uint32_t bBase = sb + bufOff + 20480u + (uint32_t)(wn * 32 * 80) + bLoff;
#pragma unroll
        for (int ks = 0; ks < 2; ks++) {
            uint32_t afh[4][4], afl[4][4];
#pragma unroll
            for (int mi = 0; mi < 4; mi++) {
                ldsm4(afh[mi], aBase + 0u     + (uint32_t)(mi * 1280 + ks * 32));
                ldsm4(afl[mi], aBase + 10240u + (uint32_t)(mi * 1280 + ks * 32));
            }
            uint32_t bfh[2][4], bfl[2][4];
#pragma unroll
            for (int np = 0; np < 2; np++) {
                ldsm4(bfh[np], bBase + 0u     + (uint32_t)(np * 1280 + ks * 32));
                ldsm4(bfl[np], bBase + 10240u + (uint32_t)(np * 1280 + ks * 32));
            }
#pragma unroll
            for (int mi = 0; mi < 4; mi++) {
#pragma unroll
                for (int ni = 0; ni < 4; ni++) {
                    const uint32_t* bh = &bfh[ni >> 1][(ni & 1) * 2];
                    const uint32_t* bl = &bfl[ni >> 1][(ni & 1) * 2];
                    mma_bf16(c[mi][ni], afh[mi], bh);
                    mma_bf16(c[mi][ni], afh[mi], bl);
                    mma_bf16(c[mi][ni], afl[mi], bh);
                }
            }
        }

        if (more) CP_WAIT0();
        __syncthreads();
    }

    const int blk = n0 >> 10;
    float* outp; const float* ev; int mode;
    switch (blk) {
        case 0:  outp = g_s.w;    ev = tdecay; mode = 4; break;
        case 1:  outp = g_s.asig; ev = taaaaa; mode = 3; break;
        case 2:  outp = g_s.ma;   ev = tmisca; mode = 3; break;
        case 3:  outp = g_s.kk;   ev = 0;      mode = 5; break;
        default: outp = g_s.mk2;  ev = tmisck; mode = 3; break;
    }
    const int erow = m0 + wm * 64 + (lane >> 2);
    const int ecol = (n0 & 1023) + wn * 32 + (lane & 3) * 2;
#pragma unroll
    for (int mi = 0; mi < 4; mi++) {
#pragma unroll
        for (int ni = 0; ni < 4; ni++) {
            const int col = ecol + ni * 8;
            const int r0 = erow + mi * 16, r1 = r0 + 8;
            float v0 = c[mi][ni][0], v1 = c[mi][ni][1];
            float v2 = c[mi][ni][2], v3 = c[mi][ni][3];
            if (mode == 4) {
                float e0 = ev[col], e1 = ev[col + 1];
                v0 = -log1pf(expf(-(e0 + v0))) - 0.5f;
                v1 = -log1pf(expf(-(e1 + v1))) - 0.5f;
                v2 = -log1pf(expf(-(e0 + v2))) - 0.5f;
                v3 = -log1pf(expf(-(e1 + v3))) - 0.5f;
            } else if (mode == 3) {
                float e0 = ev[col], e1 = ev[col + 1];
                v0 = 1.f / (1.f + expf(-(e0 + v0)));
                v1 = 1.f / (1.f + expf(-(e1 + v1)));
                v2 = 1.f / (1.f + expf(-(e0 + v2)));
                v3 = 1.f / (1.f + expf(-(e1 + v3)));
            } else {
                float2 k0 = *(const float2*)&g_s.k[(size_t)r0 * 1024 + col];
                float2 k1 = *(const float2*)&g_s.k[(size_t)r1 * 1024 + col];
                v0 += k0.x; v1 += k0.y; v2 += k1.x; v3 += k1.y;
            }
            *(float2*)&outp[(size_t)r0 * 1024 + col] = make_float2(v0, v1);
            *(float2*)&outp[(size_t)r1 * 1024 + col] = make_float2(v2, v3);
        }
    }
}

// ---------------------------------------------------------------------------
// up-projection core (CTA 32x64, cp.async dbl-buffered, chunk 32)
// ---------------------------------------------------------------------------
#define UP64_SMEM 30720

__device__ __forceinline__ void up64_body(
    const bf16* __restrict__ Ah, const bf16* __restrict__ Al,
    const bf16* __restrict__ Bh, const bf16* __restrict__ Bl,
    int m0, int n0, int tanhN, int maxcol,
    float* __restrict__ Cm, int cstride,
    bf16* __restrict__ oh, bf16* __restrict__ ol, int ostride, int ocol,
    char* sm)
{
    constexpr int B_BYTES = 64 * 80;          // 5120
    constexpr int OFF_AL = 2560;
    constexpr int OFF_BH = 5120;
    constexpr int BUF = 5120 + 2 * B_BYTES;   // 15360

    const uint32_t sb = smem_u32(sm);
    const int tid  = threadIdx.x;
    const int lane = tid & 31;
    const int wid  = tid >> 5;
    const int wm   = wid & 1;
    const int wn   = wid >> 1;

    const int arow = (tid & 127) >> 2, aq2 = tid & 3;
    const bf16* pAh = Ah + (size_t)(m0 + arow) * 1024 + aq2 * 8;
    const bf16* pAl = Al + (size_t)(m0 + arow) * 1024 + aq2 * 8;
    const uint32_t stA = (uint32_t)(arow * 80 + aq2 * 16);
    const int brow = tid >> 2;
    const bf16* pBh = Bh + (size_t)(n0 + brow) * 1024 + aq2 * 8;
    const bf16* pBl = Bl + (size_t)(n0 + brow) * 1024 + aq2 * 8;
    const uint32_t stB = (uint32_t)(brow * 80 + aq2 * 16);
    const bool doA = (tid < 128);

    const uint32_t aLoff = (uint32_t)((lane & 15) * 80 + (lane >> 4) * 16);
    const uint32_t bLoff = (uint32_t)(((lane & 7) + ((lane >> 4) & 1) * 8) * 80
                                      + ((lane >> 3) & 1) * 16);

    float c[2][4];
#pragma unroll
    for (int j = 0; j < 2; j++)
#pragma unroll
        for (int q = 0; q < 4; q++) c[j][q] = 0.f;

    {
        if (doA) {
            cp_async16(sb + stA, pAh);
            cp_async16(sb + OFF_AL + stA, pAl);
        }
        cp_async16(sb + OFF_BH + stB, pBh);
        cp_async16(sb + OFF_BH + B_BYTES + stB, pBl);
        CP_COMMIT();
        CP_WAIT0();
    }
    __syncthreads();

    for (int cidx = 0; cidx < 32; cidx++) {
        const uint32_t bufOff = (uint32_t)((cidx & 1) * BUF);
        const bool more = (cidx + 1 < 32);

        if (more) {
            const int ko = (cidx + 1) * 32;
            uint32_t d = sb + (uint32_t)(((cidx + 1) & 1) * BUF);
            if (doA) {
                cp_async16(d + stA, pAh + ko);
                cp_async16(d + OFF_AL + stA, pAl + ko);
            }
            cp_async16(d + OFF_BH + stB, pBh + ko);
            cp_async16(d + OFF_BH + B_BYTES + stB, pBl + ko);
            CP_COMMIT();
        }

        const uint32_t aBase = sb + bufOff + (uint32_t)(wm * 16 * 80) + aLoff;
#pragma unroll
        for (int ks = 0; ks < 2; ks++) {
            uint32_t afh[4], afl[4];
            ldsm4(afh, aBase + (uint32_t)(ks * 32));
            ldsm4(afl, aBase + OFF_AL + (uint32_t)(ks * 32));
            uint32_t bfh[4], bfl[4];
            const uint32_t bBase = sb + bufOff + OFF_BH
                                 + (uint32_t)(wn * 16 * 80) + bLoff
                                 + (uint32_t)(ks * 32);
            ldsm4(bfh, bBase);
            ldsm4(bfl, bBase + (uint32_t)B_BYTES);
#pragma unroll
            for (int ni = 0; ni < 2; ni++) {
                const uint32_t* bhp = &bfh[ni * 2];
                const uint32_t* blp = &bfl[ni * 2];
                mma_bf16(c[ni], afh, bhp);
                mma_bf16(c[ni], afh, blp);
                mma_bf16(c[ni], afl, bhp);
            }
        }

        if (more) CP_WAIT0();
        __syncthreads();
    }

    const int r0 = m0 + wm * 16 + (lane >> 2);
    const int r1 = r0 + 8;
#pragma unroll
    for (int ni = 0; ni < 2; ni++) {
        const int gcol = n0 + wn * 16 + ni * 8 + (lane & 3) * 2;
        float v0 = c[ni][0], v1 = c[ni][1];
        float v2 = c[ni][2], v3 = c[ni][3];
        if (gcol < tanhN) {
            v0 = tanhf(v0); v1 = tanhf(v1);
            v2 = tanhf(v2); v3 = tanhf(v3);
        }
        if (gcol < maxcol) {
            if (Cm) {
                *(float2*)&Cm[(size_t)r0 * cstride + gcol] = make_float2(v0, v1);
                *(float2*)&Cm[(size_t)r1 * cstride + gcol] = make_float2(v2, v3);
            }
            if (oh) {
                uint32_t h0, l0, h1, l1;
                split2(v0, v1, h0, l0);
                split2(v2, v3, h1, l1);
                *(uint32_t*)&oh[(size_t)r0 * ostride + ocol + gcol] = h0;
                *(uint32_t*)&ol[(size_t)r0 * ostride + ocol + gcol] = l0;
                *(uint32_t*)&oh[(size_t)r1 * ostride + ocol + gcol] = h1;
                *(uint32_t*)&ol[(size_t)r1 * ostride + ocol + gcol] = l1;
            }
        }
    }
}

// mixin up-projection: writes bf16 hi/lo (mixinh/mixinl, stride 128)
__global__ void __launch_bounds__(256)
gemm_up_mix()
{
    extern __shared__ __align__(16) char sm[];
    up64_body(g_s.xmixh, g_s.xmixl, g_s.mw1Th, g_s.mw1Tl,
              blockIdx.x * 32, blockIdx.y * 64, 128, 128,
              0, 0, g_s.mixinh, g_s.mixinl, 128, 0, sm);
}

// batched post-mix up-projections: y 0-1 gate1, 2-3 lora_wa, 4 lora_k
__global__ void __launch_bounds__(256)
gemm_up_batch()
{
    extern __shared__ __align__(16) char sm[];
    const int y = blockIdx.y;
    const int m0 = blockIdx.x * 32;
    if (y < 2) {
        up64_body(g_s.xrgh, g_s.xrgl, g_s.gw1Th, g_s.gw1Tl,
                  m0, y * 64, 128, 128,
                  0, 0, g_s.g1h, g_s.g1l, 128, 0, sm);
    } else if (y < 4) {
        up64_body(g_s.xwah, g_s.xwal, g_s.waTh, g_s.waTl,
                  m0, (y - 2) * 64, 64, 128,
                  0, 0, g_s.loraAh, g_s.loraAl, 160, 0, sm);
    } else {
        up64_body(g_s.xkh, g_s.xkl, g_s.kTh, g_s.kTl,
                  m0, 0, 16, 32,
                  0, 0, g_s.loraAh, g_s.loraAl, 160, 128, sm);
    }
}

// ---------------------------------------------------------------------------
// conv4: 4 weight matrices fp32 -> bf16 hi/lo in one launch
// ---------------------------------------------------------------------------
__global__ void __launch_bounds__(256)
conv4(const float* __restrict__ w0, const float* __restrict__ w1,
      const float* __restrict__ w2, const float* __restrict__ w3)
{
    const int wq = blockIdx.x >> 10;
    const int i  = (blockIdx.x & 1023) * 256 + threadIdx.x;
    const float* src; bf16 *dh, *dl;
    switch (wq) {
        case 0:  src = w0; dh = g_s.wrh; dl = g_s.wrl; break;
        case 1:  src = w1; dh = g_s.wkh; dl = g_s.wkl; break;
        case 2:  src = w2; dh = g_s.wvh; dl = g_s.wvl; break;
        default: src = w3; dh = g_s.woh; dl = g_s.wol; break;
    }
    uint2 hh, ll;
    split4(((const float4*)src)[i], hh, ll);
    ((uint2*)dh)[i] = hh;
    ((uint2*)dl)[i] = ll;
}

// ---------------------------------------------------------------------------
// transconv / packT / pack_bigB / pack_mix
// ---------------------------------------------------------------------------
__global__ void __launch_bounds__(256)
transconv_kernel(const float* __restrict__ src, bf16* __restrict__ dh,
                 bf16* __restrict__ dl)
{
    __shared__ float tile[32][33];
    int bx = blockIdx.x;
    int by = blockIdx.y;
    int tx = threadIdx.x & 31, ty = threadIdx.x >> 5;
#pragma unroll
    for (int i = 0; i < 4; i++)
        tile[ty + i * 8][tx] = src[(size_t)(by * 32 + ty + i * 8) * 1024 + bx * 32 + tx];
    __syncthreads();
#pragma unroll
    for (int i = 0; i < 4; i++) {
        float v = tile[tx][ty + i * 8];
        bf16 hv, lv; splitf(v, hv, lv);
        size_t di = (size_t)(bx * 32 + ty + i * 8) * 128 + by * 32 + tx;
        dh[di] = hv; dl[di] = lv;
    }
}

__global__ void __launch_bounds__(256)
packT_w1(const float* __restrict__ src, bf16* __restrict__ dh,
         bf16* __restrict__ dl)
{
    int idx = blockIdx.x * 256 + threadIdx.x;
    int cth = idx >> 10, r = idx & 1023;
    bf16 hv, lv; splitf(src[(size_t)r * 128 + cth], hv, lv);
    dh[idx] = hv; dl[idx] = lv;
}

// pack_mix: blocks 0-511 = maa_w1 transpose; 512-1023 = W2 block-transpose
__global__ void __launch_bounds__(256)
pack_mix(const float* __restrict__ w1, const float* __restrict__ w2)
{
    const int b = blockIdx.x;
    if (b < 512) {
        int idx = b * 256 + threadIdx.x;          // 128*1024
        int cth = idx >> 10, r = idx & 1023;
        bf16 hv, lv; splitf(w1[(size_t)r * 128 + cth], hv, lv);
        g_s.mw1Th[idx] = hv; g_s.mw1Tl[idx] = lv;
    } else {
        int idx = (b - 512) * 256 + threadIdx.x;  // 4096*32
        int n = idx >> 5, kq = idx & 31;
        int f = n >> 10, nloc = n & 1023;
        bf16 hv, lv;
        splitf(w2[(size_t)(f * 32 + kq) * 1024 + nloc], hv, lv);
        g_s.w2Th[idx] = hv; g_s.w2Tl[idx] = lv;
    }
}

__global__ void __launch_bounds__(256)
packT_wa(const float* __restrict__ dw1, const float* __restrict__ aw1,
         const float* __restrict__ maw1)
{
    int idx = blockIdx.x * 256 + threadIdx.x;
    int cth = idx >> 10, r = idx & 1023;
    float v = 0.f;
    if (cth < 64)      v = dw1[r * 64 + cth];
    else if (cth < 80) v = aw1[r * 16 + (cth - 64)];
    else if (cth < 96) v = maw1[r * 16 + (cth - 80)];
    bf16 hv, lv; splitf(v, hv, lv);
    g_s.waTh[idx] = hv; g_s.waTl[idx] = lv;
}
__global__ void __launch_bounds__(256)
packT_k(const float* __restrict__ kw1, const float* __restrict__ mkw1)
{
    int idx = blockIdx.x * 256 + threadIdx.x;   // 64*1024
    int cth = idx >> 10, r = idx & 1023;
    float v = 0.f;
    if (cth < 16)      v = kw1[r * 16 + cth];
    else if (cth < 32) v = mkw1[r * 16 + (cth - 16)];
    bf16 hv, lv; splitf(v, hv, lv);
    g_s.kTh[idx] = hv; g_s.kTl[idx] = lv;
}

__global__ void __launch_bounds__(256)
pack_bigB(const float* __restrict__ dw2, const float* __restrict__ aw2,
          const float* __restrict__ maw2, const float* __restrict__ kw2,
          const float* __restrict__ mkw2)
{
    int idx = blockIdx.x * 256 + threadIdx.x;
    int n = idx / 160, kq = idx - (idx / 160) * 160;
    int blk = n >> 10, nloc = n & 1023;
    float v = 0.f;
    switch (blk) {
        case 0: if (kq < 64)               v = dw2 [(size_t)kq * 1024 + nloc]; break;
        case 1: if (kq >= 64 && kq < 80)   v = aw2 [(size_t)(kq - 64) * 1024 + nloc]; break;
        case 2: if (kq >= 80 && kq < 96)   v = maw2[(size_t)(kq - 80) * 1024 + nloc]; break;
        case 3: if (kq >= 128 && kq < 144) v = kw2 [(size_t)(kq - 128) * 1024 + nloc]; break;
        default:if (kq >= 144)             v = mkw2[(size_t)(kq - 144) * 1024 + nloc]; break;
    }
    bf16 hv, lv; splitf(v, hv, lv);
    g_s.bigBh[idx] = hv; g_s.bigBl[idx] = lv;
}

// ---------------------------------------------------------------------------
// ew0
// ---------------------------------------------------------------------------
__global__ void __launch_bounds__(256)
ew0_kernel(const float* __restrict__ x, const float* __restrict__ maa_x)
{
    size_t i4  = (size_t)blockIdx.x * 256 + threadIdx.x;
    size_t idx = i4 * 4;
    int c    = (int)(idx & (CC - 1));
    int nrow = (int)(idx >> 10);
    float4 xv = *(const float4*)&x[idx];
    float4 xp = make_float4(0.f, 0.f, 0.f, 0.f);
    if (nrow & (TT - 1))
        xp = *(const float4*)&x[idx - CC];
    float4 mv = *(const float4*)&maa_x[c];
    float4 d, xm;
    d.x = xp.x - xv.x;  xm.x = xv.x + d.x * mv.x;
    d.y = xp.y - xv.y;  xm.y = xv.y + d.y * mv.y;
    d.z = xp.z - xv.z;  xm.z = xv.z + d.z * mv.z;
    d.w = xp.w - xv.w;  xm.w = xv.w + d.w * mv.w;
    *(float4*)&g_s.xx[idx] = d;
    uint2 h, l;
    split4(xm, h, l);
    *(uint2*)&g_s.xmixh[idx] = h;
    *(uint2*)&g_s.xmixl[idx] = l;
}

// ---------------------------------------------------------------------------
// combine
// ---------------------------------------------------------------------------
__global__ void __launch_bounds__(256)
combine_kernel()
{
    int n   = blockIdx.x;
    int tid = threadIdx.x;
    size_t off = (size_t)n * CC + tid * 4;

    float4 kkv = *(float4*)&g_s.kk[off];
    float ss = kkv.x*kkv.x + kkv.y*kkv.y + kkv.z*kkv.z + kkv.w*kkv.w;
#pragma unroll
    for (int o = 8; o; o >>= 1) ss += __shfl_xor_sync(0xffffffffu, ss, o, 16);
    float inv = 1.f / fmaxf(sqrtf(ss), 1e-12f);

    float4 kq = *(float4*)&g_s.k[off];
    float4 aq = *(float4*)&g_s.asig[off];
    float4 mq = *(float4*)&g_s.ma[off];
    float4 wq = *(float4*)&g_s.w[off];
    float4 mk = *(float4*)&g_s.mk2[off];
    float4 kfv, ddv, avv, bvv;
#define CMB(X) { float fac = mq.X + aq.X * (1.f - mq.X); \
    float ee = expf(fminf(wq.X * mk.X, 0.f)); \
    kfv.X = kq.X * fac * ee; \
    ddv.X = expf(wq.X); \
    float kn = kkv.X * inv; \
    avv.X = -kn; bvv.X = kn * aq.X; }
    CMB(x) CMB(y) CMB(z) CMB(w)
#undef CMB
    *(float4*)&g_s.kf[off] = kfv;
    *(float4*)&g_s.dd[off] = ddv;
    *(float4*)&g_s.av[off] = avv;
    *(float4*)&g_s.bv[off] = bvv;
}

// ---------------------------------------------------------------------------
// WKV-7 scan: cp.async 3-deep pipeline
// ---------------------------------------------------------------------------
__global__ void __launch_bounds__(256)
wkv_kernel()
{
    const int blk = blockIdx.x;
    const int b = blk >> 4;
    const int h = blk & 15;
    const int tid = threadIdx.x;
    const int i  = tid >> 2;
    const int jq = tid & 3;

    __shared__ __align__(16) float sb[4][6][64];
    const size_t rowbase = ((size_t)b * TT) * CC + h * NN;

    const float* gsrc = 0;
    uint32_t sdst[4];
    if (tid < 96) {
        int larr = tid >> 4, lq = tid & 15;
        const float* srcs[6] = { g_s.r, g_s.dd, g_s.kf, g_s.av, g_s.bv, g_s.v };
        gsrc = srcs[larr] + rowbase + lq * 4;
#pragma unroll
        for (int q = 0; q < 4; q++) sdst[q] = smem_u32(&sb[q][larr][lq * 4]);
    }

#pragma unroll
    for (int pre = 0; pre < 3; pre++) {
        if (tid < 96) cp_async16(sdst[pre], gsrc + (size_t)pre * CC);
        CP_COMMIT();
    }

    unsigned long long S2[8];
#pragma unroll
    for (int u = 0; u < 8; u++) S2[u] = 0ull;

    float* yout = g_s.y + rowbase + i;

    for (int t = 0; t < TT; t++) {
        CP_WAIT2();
        __syncthreads();
        const int p = t & 3;

        const ulonglong2* r2p = (const ulonglong2*)(sb[p][0] + jq * 16);
        const ulonglong2* d2p = (const ulonglong2*)(sb[p][1] + jq * 16);
        const ulonglong2* k2p = (const ulonglong2*)(sb[p][2] + jq * 16);
        const ulonglong2* a2p = (const ulonglong2*)(sb[p][3] + jq * 16);
        const ulonglong2* b2p = (const ulonglong2*)(sb[p][4] + jq * 16);
        const float vi = sb[p][5][i];

        ulonglong2 Rv[4], Dv[4], Kv[4], Av[4], Bv[4];
#pragma unroll
        for (int u = 0; u < 4; u++) {
            Rv[u] = r2p[u]; Dv[u] = d2p[u]; Kv[u] = k2p[u];
            Av[u] = a2p[u]; Bv[u] = b2p[u];
        }

        if (tid < 96 && t + 3 < TT)
            cp_async16(sdst[(t + 3) & 3], gsrc + (size_t)(t + 3) * CC);
        CP_COMMIT();

        unsigned long long sa0 = 0ull, sa1 = 0ull, pp0 = 0ull, pp1 = 0ull;
        unsigned long long br0 = 0ull, br1 = 0ull, kr0 = 0ull, kr1 = 0ull;
#pragma unroll
        for (int u = 0; u < 4; u++) {
            unsigned long long drx = mul2(Dv[u].x, Rv[u].x);
            unsigned long long dry = mul2(Dv[u].y, Rv[u].y);
            fma2(sa0, S2[2*u],   Av[u].x);
            fma2(sa1, S2[2*u+1], Av[u].y);
            fma2(pp0, S2[2*u],   drx);
            fma2(pp1, S2[2*u+1], dry);
            fma2(br0, Bv[u].x, Rv[u].x);
            fma2(br1, Bv[u].y, Rv[u].y);
            fma2(kr0, Kv[u].x, Rv[u].x);
            fma2(kr1, Kv[u].y, Rv[u].y);
        }
        float sa = hadd4(sa0, sa1);
        float pp = hadd4(pp0, pp1);
        float br = hadd4(br0, br1);
        float kr = hadd4(kr0, kr1);
        sa += __shfl_xor_sync(0xffffffffu, sa, 1, 4);
        pp += __shfl_xor_sync(0xffffffffu, pp, 1, 4);
        br += __shfl_xor_sync(0xffffffffu, br, 1, 4);
        kr += __shfl_xor_sync(0xffffffffu, kr, 1, 4);
        sa += __shfl_xor_sync(0xffffffffu, sa, 2, 4);
        pp += __shfl_xor_sync(0xffffffffu, pp, 2, 4);
        br += __shfl_xor_sync(0xffffffffu, br, 2, 4);
        kr += __shfl_xor_sync(0xffffffffu, kr, 2, 4);

        if (jq == 0) yout[(size_t)t * CC] = pp + sa * br + vi * kr;

        const unsigned long long sa2 = dup2(sa);
        const unsigned long long v2  = dup2(vi);
#pragma unroll
        for (int u = 0; u < 4; u++) {
            S2[2*u]   = fma2g(S2[2*u],   Dv[u].x,
                              fma2g(sa2, Bv[u].x, mul2(v2, Kv[u].x)));
            S2[2*u+1] = fma2g(S2[2*u+1], Dv[u].y,
                              fma2g(sa2, Bv[u].y, mul2(v2, Kv[u].y)));
        }
    }
}

// ---------------------------------------------------------------------------
// post: GroupNorm + bonus + gate -> z (bf16 hi/lo)
// ---------------------------------------------------------------------------
__global__ void __launch_bounds__(256)
post_kernel(const float* __restrict__ faaaa,
            const float* __restrict__ lnw, const float* __restrict__ lnb)
{
    int n   = blockIdx.x;
    int tid = threadIdx.x;
    int c   = tid * 4;
    size_t off = (size_t)n * CC + c;

    float4 yv = *(float4*)&g_s.y [off];
    float4 rv = *(float4*)&g_s.r [off];
    float4 kv = *(float4*)&g_s.kf[off];
    float4 vv = *(float4*)&g_s.v [off];
    float4 gv = *(float4*)&g_s.g [off];
    float4 fv = *(const float4*)&faaaa[c];

    float s  = yv.x + yv.y + yv.z + yv.w;
    float s2 = yv.x*yv.x + yv.y*yv.y + yv.z*yv.z + yv.w*yv.w;
    float dk = rv.x*kv.x*fv.x + rv.y*kv.y*fv.y + rv.z*kv.z*fv.z + rv.w*kv.w*fv.w;
#pragma unroll
    for (int o = 8; o; o >>= 1) {
        s  += __shfl_xor_sync(0xffffffffu, s,  o, 16);
        s2 += __shfl_xor_sync(0xffffffffu, s2, o, 16);
        dk += __shfl_xor_sync(0xffffffffu, dk, o, 16);
    }
    float mean = s  * (1.f / 64.f);
    float var  = s2 * (1.f / 64.f) - mean * mean;
    float rs   = rsqrtf(var + 64e-5f);

    float4 lw = *(const float4*)&lnw[c];
    float4 lb = *(const float4*)&lnb[c];
    float4 z;
    z.x = (((yv.x - mean) * rs) * lw.x + lb.x + dk * vv.x) * gv.x;
    z.y = (((yv.y - mean) * rs) * lw.y + lb.y + dk * vv.y) * gv.y;
    z.z = (((yv.z - mean) * rs) * lw.z + lb.z + dk * vv.z) * gv.z;
    z.w = (((yv.w - mean) * rs) * lw.w + lb.w + dk * vv.w) * gv.w;
    uint2 h, l;
    split4(z, h, l);
    *(uint2*)&g_s.zh[off] = h;
    *(uint2*)&g_s.zl[off] = l;
}

// ---------------------------------------------------------------------------
// Host orchestration
// ---------------------------------------------------------------------------
static void gmma(const bf16* Ah, const bf16* Al, const bf16* Bh,
                 const bf16* Bl, float* Cp, int K)
{
    dim3 grid(8, MM / 128);
    gemm_mma2<<<grid, 256, MMA_SMEM>>>(Ah, Al, Bh, Bl, Cp, K);
}

extern "C" void kernel_launch(void* const* d_in, const int* in_sizes, int n_in,
                              void* d_out, int out_size)
{
    const float* x       = (const float*)d_in[0];
    const float* maa_x   = (const float*)d_in[1];
    const float* maa_rg  = (const float*)d_in[2];
    const float* maa_wa  = (const float*)d_in[3];
    const float* maa_k   = (const float*)d_in[4];
    const float* maa_v   = (const float*)d_in[5];
    const float* maa_w1  = (const float*)d_in[6];
    const float* maa_w2  = (const float*)d_in[7];
    const float* tdecay  = (const float*)d_in[8];
    const float* dw1     = (const float*)d_in[9];
    const float* dw2     = (const float*)d_in[10];
    const float* faaaa   = (const float*)d_in[11];
    const float* taaaaa  = (const float*)d_in[12];
    const float* aw1     = (const float*)d_in[13];
    const float* aw2     = (const float*)d_in[14];
    const float* kw1     = (const float*)d_in[15];
    const float* kw2     = (const float*)d_in[16];
    const float* gw1     = (const float*)d_in[17];
    const float* gw2     = (const float*)d_in[18];
    const float* maw1    = (const float*)d_in[19];
    const float* maw2    = (const float*)d_in[20];
    const float* tmisca  = (const float*)d_in[21];
    const float* mkw1    = (const float*)d_in[22];
    const float* mkw2    = (const float*)d_in[23];
    const float* tmisck  = (const float*)d_in[24];
    const float* wr      = (const float*)d_in[25];
    const float* wk      = (const float*)d_in[26];
    const float* wv      = (const float*)d_in[27];
    const float* wo      = (const float*)d_in[28];
    const float* lnw     = (const float*)d_in[29];
    const float* lnb     = (const float*)d_in[30];
    float* out = (float*)d_out;
    (void)in_sizes; (void)n_in; (void)out_size;

    Scratch* S = nullptr;
    cudaGetSymbolAddress((void**)&S, g_s);
    cudaFuncSetAttribute(gemm_mma2, cudaFuncAttributeMaxDynamicSharedMemorySize,
                         MMA_SMEM);
    cudaFuncSetAttribute(gemm_rkv, cudaFuncAttributeMaxDynamicSharedMemorySize,
                         MMA_SMEM);
    cudaFuncSetAttribute(gemm_down, cudaFuncAttributeMaxDynamicSharedMemorySize,
                         MMA_SMEM);
    cudaFuncSetAttribute(gemm_mix_mma,
                         cudaFuncAttributeMaxDynamicSharedMemorySize, MIXMMA_SMEM);
    cudaFuncSetAttribute(gemm_up_mix,
                         cudaFuncAttributeMaxDynamicSharedMemorySize, UP64_SMEM);
    cudaFuncSetAttribute(gemm_up_batch,
                         cudaFuncAttributeMaxDynamicSharedMemorySize, UP64_SMEM);

    // 1-4: ncu captures the 4th launch -> gemm_mix_mma
    ew0_kernel<<<(MM * CC / 4) / 256, 256>>>(x, maa_x);                  // 1
    pack_mix<<<1024, 256>>>(maa_w1, maa_w2);                             // 2
    gemm_up_mix<<<dim3(128, 2), 256, UP64_SMEM>>>();                     // 3
    gemm_mix_mma<<<dim3(32, 32), 256, MIXMMA_SMEM>>>(x,                  // 4
        maa_rg, maa_wa, maa_k, maa_v);

    // weight conversions / packs
    conv4<<<4096, 256>>>(wr, wk, wv, wo);
    packT_w1<<<512, 256>>>(gw1, S->gw1Th, S->gw1Tl);
    packT_wa<<<512, 256>>>(dw1, aw1, maw1);
    packT_k<<<256, 256>>>(kw1, mkw1);
    transconv_kernel<<<dim3(32, 4), 256>>>(gw2, S->gw2Th, S->gw2Tl);
    pack_bigB<<<(5120 * 160) / 256, 256>>>(dw2, aw2, maw2, kw2, mkw2);

    // big projections (r, k, v) batched in one launch
    gemm_rkv<<<dim3(8, 32, 3), 256, MMA_SMEM>>>();

    // batched up-projections (gate1 + lora_wa + lora_k)
    gemm_up_batch<<<dim3(128, 5), 256, UP64_SMEM>>>();

    // gate down-projection
    gmma(S->g1h, S->g1l, S->gw2Th, S->gw2Tl, S->g, 128);

    // fused block-diagonal LoRA down-projection
    gemm_down<<<dim3(40, 32), 256, MMA_SMEM>>>(tdecay, taaaaa, tmisca, tmisck);

    // combine + scan + post + output
    combine_kernel<<<MM, 256>>>();
    wkv_kernel<<<BB * HH, 256>>>();
    post_kernel<<<MM, 256>>>(faaaa, lnw, lnb);
    gmma(S->zh, S->zl, S->woh, S->wol, out, 1024);
}

// round 17
// speedup vs baseline: 1.0173x; 1.0173x over previous
#include <cuda_runtime.h>
#include <cuda_bf16.h>
#include <math.h>
#include <stdint.h>
#include <string.h>

#define BB 4
#define TT 1024
#define CC 1024
#define HH 16
#define NN 64
#define MM (BB*TT)   // 4096 rows

typedef __nv_bfloat16 bf16;

// ---------------------------------------------------------------------------
// Scratch (static device memory)
// ---------------------------------------------------------------------------
struct Scratch {
    float xx   [MM*CC];
    float r    [MM*CC];
    float k    [MM*CC];
    float v    [MM*CC];
    float g    [MM*CC];
    float w    [MM*CC];
    float kk   [MM*CC];
    float asig [MM*CC];
    float ma   [MM*CC];
    float mk2  [MM*CC];
    float kf   [MM*CC];
    float dd   [MM*CC];
    float av   [MM*CC];
    float bv   [MM*CC];
    float y    [MM*CC];
    // bf16 hi/lo activations
    bf16 xmixh[MM*CC], xmixl[MM*CC];
    bf16 mixinh[MM*128], mixinl[MM*128];
    bf16 xrgh[MM*CC], xrgl[MM*CC];
    bf16 xwah[MM*CC], xwal[MM*CC];
    bf16 xkh [MM*CC], xkl [MM*CC];
    bf16 xvh [MM*CC], xvl [MM*CC];
    bf16 zh  [MM*CC], zl  [MM*CC];
    bf16 g1h [MM*128], g1l [MM*128];
    bf16 loraAh[MM*160], loraAl[MM*160];
    // bf16 hi/lo weights
    bf16 wrh[CC*CC], wrl[CC*CC];
    bf16 wkh[CC*CC], wkl[CC*CC];
    bf16 wvh[CC*CC], wvl[CC*CC];
    bf16 woh[CC*CC], wol[CC*CC];
    bf16 gw2Th[CC*128], gw2Tl[CC*128];
    bf16 mw1Th[128*1024], mw1Tl[128*1024];
    bf16 w2Th[4096*32],  w2Tl[4096*32];
    bf16 gw1Th[128*1024], gw1Tl[128*1024];
    bf16 waTh [128*1024], waTl [128*1024];
    bf16 kTh  [64*1024],  kTl  [64*1024];
    bf16 bigBh[5120*160], bigBl[5120*160];
};
__device__ Scratch g_s;

// ---------------------------------------------------------------------------
// Packed f32x2 helpers
// ---------------------------------------------------------------------------
__device__ __forceinline__ unsigned long long dup2(float x) {
    unsigned long long r;
    asm("mov.b64 %0, {%1, %1};" : "=l"(r) : "f"(x));
    return r;
}
__device__ __forceinline__ void fma2(unsigned long long& acc,
                                     unsigned long long a,
                                     unsigned long long b) {
    asm("fma.rn.f32x2 %0, %1, %2, %0;" : "+l"(acc) : "l"(a), "l"(b));
}
__device__ __forceinline__ unsigned long long fma2g(unsigned long long a,
                                                    unsigned long long b,
                                                    unsigned long long c) {
    unsigned long long d;
    asm("fma.rn.f32x2 %0, %1, %2, %3;" : "=l"(d) : "l"(a), "l"(b), "l"(c));
    return d;
}
__device__ __forceinline__ unsigned long long mul2(unsigned long long a,
                                                   unsigned long long b) {
    unsigned long long d;
    asm("mul.rn.f32x2 %0, %1, %2;" : "=l"(d) : "l"(a), "l"(b));
    return d;
}
__device__ __forceinline__ float2 unpack2(unsigned long long v) {
    float2 f;
    asm("mov.b64 {%0, %1}, %2;" : "=f"(f.x), "=f"(f.y) : "l"(v));
    return f;
}
__device__ __forceinline__ float hadd4(unsigned long long a,
                                       unsigned long long b) {
    float2 f = unpack2(a), g = unpack2(b);
    return (f.x + f.y) + (g.x + g.y);
}
__device__ __forceinline__ uint32_t smem_u32(const void* p) {
    uint32_t a;
    asm("{ .reg .u64 t; cvta.to.shared.u64 t, %1; cvt.u32.u64 %0, t; }"
        : "=r"(a) : "l"(p));
    return a;
}

// cp.async helpers
__device__ __forceinline__ void cp_async16(uint32_t saddr, const void* gptr) {
    asm volatile("cp.async.cg.shared.global [%0], [%1], 16;"
        :: "r"(saddr), "l"(gptr) : "memory");
}
#define CP_COMMIT() asm volatile("cp.async.commit_group;" ::: "memory")
#define CP_WAIT0()  asm volatile("cp.async.wait_group 0;" ::: "memory")
#define CP_WAIT2()  asm volatile("cp.async.wait_group 2;" ::: "memory")

// hi/lo splits
__device__ __forceinline__ void split4(float4 f, uint2& h, uint2& l) {
    __nv_bfloat162 h01 = __floats2bfloat162_rn(f.x, f.y);
    __nv_bfloat162 h23 = __floats2bfloat162_rn(f.z, f.w);
    float lx = f.x - __bfloat162float(h01.x);
    float ly = f.y - __bfloat162float(h01.y);
    float lz = f.z - __bfloat162float(h23.x);
    float lw = f.w - __bfloat162float(h23.y);
    __nv_bfloat162 l01 = __floats2bfloat162_rn(lx, ly);
    __nv_bfloat162 l23 = __floats2bfloat162_rn(lz, lw);
    memcpy(&h.x, &h01, 4); memcpy(&h.y, &h23, 4);
    memcpy(&l.x, &l01, 4); memcpy(&l.y, &l23, 4);
}
__device__ __forceinline__ void split2(float a, float b,
                                       uint32_t& h, uint32_t& l) {
    __nv_bfloat162 hh = __floats2bfloat162_rn(a, b);
    float la = a - __bfloat162float(hh.x);
    float lb = b - __bfloat162float(hh.y);
    __nv_bfloat162 ll = __floats2bfloat162_rn(la, lb);
    memcpy(&h, &hh, 4); memcpy(&l, &ll, 4);
}
__device__ __forceinline__ void splitf(float v, bf16& h, bf16& l) {
    h = __float2bfloat16_rn(v);
    l = __float2bfloat16_rn(v - __bfloat162float(h));
}

// ---------------------------------------------------------------------------
// mma.sync / ldmatrix helpers
// ---------------------------------------------------------------------------
__device__ __forceinline__ void ldsm4(uint32_t* r, uint32_t addr) {
    asm volatile("ldmatrix.sync.aligned.m8n8.x4.shared.b16 {%0,%1,%2,%3}, [%4];"
        : "=r"(r[0]), "=r"(r[1]), "=r"(r[2]), "=r"(r[3]) : "r"(addr));
}
__device__ __forceinline__ void mma_bf16(float* c, const uint32_t* a,
                                         const uint32_t* b) {
    asm volatile("mma.sync.aligned.m16n8k16.row.col.f32.bf16.bf16.f32 "
        "{%0,%1,%2,%3}, {%4,%5,%6,%7}, {%8,%9}, {%0,%1,%2,%3};"
        : "+f"(c[0]), "+f"(c[1]), "+f"(c[2]), "+f"(c[3])
        : "r"(a[0]), "r"(a[1]), "r"(a[2]), "r"(a[3]), "r"(b[0]), "r"(b[1]));
}

// ---------------------------------------------------------------------------
// gemm_mma2: C[M,1024] = (Ah+Al)[M,K] @ (Bh+Bl)[1024,K]^T, fp32 accum.
// ---------------------------------------------------------------------------
#define MMA_SMEM 81920

__global__ void __launch_bounds__(256, 2)
gemm_mma2(const bf16* __restrict__ Ah, const bf16* __restrict__ Al,
          const bf16* __restrict__ Bh, const bf16* __restrict__ Bl,
          float* __restrict__ Cm, int K)
{
    extern __shared__ __align__(16) char sm[];
    const uint32_t sb = smem_u32(sm);

    const int tid  = threadIdx.x;
    const int lane = tid & 31;
    const int wid  = tid >> 5;
    const int wm   = wid & 1;
    const int wn   = wid >> 1;
    const int n0 = blockIdx.x * 128;
    const int m0 = blockIdx.y * 128;

    const int row = tid >> 1, half = tid & 1;
    const bf16* pAh = Ah + (size_t)(m0 + row) * K + half * 16;
    const bf16* pAl = Al + (size_t)(m0 + row) * K + half * 16;
    const bf16* pBh = Bh + (size_t)(n0 + row) * K + half * 16;
    const bf16* pBl = Bl + (size_t)(n0 + row) * K + half * 16;
    const uint32_t st = (uint32_t)(row * 80 + half * 32);

    const uint32_t aLoff = (uint32_t)((lane & 15) * 80 + (lane >> 4) * 16);
    const uint32_t bLoff = (uint32_t)(((lane & 7) + ((lane >> 4) & 1) * 8) * 80
                                      + ((lane >> 3) & 1) * 16);

    float c[4][4][4];
#pragma unroll
    for (int i = 0; i < 4; i++)
#pragma unroll
        for (int j = 0; j < 4; j++)
#pragma unroll
            for (int q = 0; q < 4; q++) c[i][j][q] = 0.f;

    const int chunks = K >> 5;

    {
        uint32_t d = sb + st;
        cp_async16(d,             pAh); cp_async16(d + 16,         pAh + 8);
        cp_async16(d + 10240,     pAl); cp_async16(d + 10240 + 16, pAl + 8);
        cp_async16(d + 20480,     pBh); cp_async16(d + 20480 + 16, pBh + 8);
        cp_async16(d + 30720,     pBl); cp_async16(d + 30720 + 16, pBl + 8);
        CP_COMMIT();
        CP_WAIT0();
    }
    __syncthreads();

    for (int cidx = 0; cidx < chunks; cidx++) {
        const uint32_t bufOff = (uint32_t)((cidx & 1) * 40960);
        const bool more = (cidx + 1 < chunks);

        if (more) {
            const int ko = (cidx + 1) * 32;
            uint32_t d = sb + (uint32_t)(((cidx + 1) & 1) * 40960) + st;
            cp_async16(d,             pAh + ko); cp_async16(d + 16,         pAh + ko + 8);
            cp_async16(d + 10240,     pAl + ko); cp_async16(d + 10240 + 16, pAl + ko + 8);
            cp_async16(d + 20480,     pBh + ko); cp_async16(d + 20480 + 16, pBh + ko + 8);
            cp_async16(d + 30720,     pBl + ko); cp_async16(d + 30720 + 16, pBl + ko + 8);
            CP_COMMIT();
        }

        const uint32_t aBase = sb + bufOff + (uint32_t)(wm * 64 * 80) + aLoff;
        const uint32_t bBase = sb + bufOff + 20480u + (uint32_t)(wn * 32 * 80) + bLoff;
#pragma unroll
        for (int ks = 0; ks < 2; ks++) {
            uint32_t afh[4][4], afl[4][4];
#pragma unroll
            for (int mi = 0; mi < 4; mi++) {
                ldsm4(afh[mi], aBase + 0u     + (uint32_t)(mi * 1280 + ks * 32));
                ldsm4(afl[mi], aBase + 10240u + (uint32_t)(mi * 1280 + ks * 32));
            }
            uint32_t bfh[2][4], bfl[2][4];
#pragma unroll
            for (int np = 0; np < 2; np++) {
                ldsm4(bfh[np], bBase + 0u     + (uint32_t)(np * 1280 + ks * 32));
                ldsm4(bfl[np], bBase + 10240u + (uint32_t)(np * 1280 + ks * 32));
            }
#pragma unroll
            for (int mi = 0; mi < 4; mi++) {
#pragma unroll
                for (int ni = 0; ni < 4; ni++) {
                    const uint32_t* bh = &bfh[ni >> 1][(ni & 1) * 2];
                    const uint32_t* bl = &bfl[ni >> 1][(ni & 1) * 2];
                    mma_bf16(c[mi][ni], afh[mi], bh);
                    mma_bf16(c[mi][ni], afh[mi], bl);
                    mma_bf16(c[mi][ni], afl[mi], bh);
                }
            }
        }

        if (more) CP_WAIT0();
        __syncthreads();
    }

    const int erow = m0 + wm * 64 + (lane >> 2);
    const int ecol = n0 + wn * 32 + (lane & 3) * 2;
#pragma unroll
    for (int mi = 0; mi < 4; mi++) {
#pragma unroll
        for (int ni = 0; ni < 4; ni++) {
            size_t base0 = (size_t)(erow + mi * 16)     * 1024 + ecol + ni * 8;
            size_t base1 = (size_t)(erow + mi * 16 + 8) * 1024 + ecol + ni * 8;
            *(float2*)&Cm[base0] = make_float2(c[mi][ni][0], c[mi][ni][1]);
            *(float2*)&Cm[base1] = make_float2(c[mi][ni][2], c[mi][ni][3]);
        }
    }
}

// ---------------------------------------------------------------------------
// gemm_mix_mma: batched token-mix GEMM + epilogue, HMMA.
// ---------------------------------------------------------------------------
#define MIXMMA_SMEM 40960

__global__ void __launch_bounds__(256, 2)
gemm_mix_mma(const float* __restrict__ x,
             const float* __restrict__ m_rg, const float* __restrict__ m_wa,
             const float* __restrict__ m_k,  const float* __restrict__ m_v)
{
    extern __shared__ __align__(16) char sm[];
    const uint32_t sb = smem_u32(sm);

    const int tid  = threadIdx.x;
    const int lane = tid & 31;
    const int wid  = tid >> 5;
    const int wm   = wid & 1;
    const int wn   = wid >> 1;
    const int n0 = blockIdx.x * 128;
    const int m0 = blockIdx.y * 128;
    const int f  = n0 >> 10;
    const int col0 = n0 & 1023;

    const int row = tid >> 1, half = tid & 1;
    {
        const bf16* pAh = g_s.mixinh + (size_t)(m0 + row) * 128 + f * 32 + half * 16;
        const bf16* pAl = g_s.mixinl + (size_t)(m0 + row) * 128 + f * 32 + half * 16;
        const bf16* pBh = g_s.w2Th + (size_t)(n0 + row) * 32 + half * 16;
        const bf16* pBl = g_s.w2Tl + (size_t)(n0 + row) * 32 + half * 16;
        const uint32_t d = sb + (uint32_t)(row * 80 + half * 32);
        cp_async16(d,             pAh); cp_async16(d + 16,         pAh + 8);
        cp_async16(d + 10240,     pAl); cp_async16(d + 10240 + 16, pAl + 8);
        cp_async16(d + 20480,     pBh); cp_async16(d + 20480 + 16, pBh + 8);
        cp_async16(d + 30720,     pBl); cp_async16(d + 30720 + 16, pBl + 8);
        CP_COMMIT();
        CP_WAIT0();
    }
    __syncthreads();

    const uint32_t aLoff = (uint32_t)((lane & 15) * 80 + (lane >> 4) * 16);
    const uint32_t bLoff = (uint32_t)(((lane & 7) + ((lane >> 4) & 1) * 8) * 80
                                      + ((lane >> 3) & 1) * 16);

    float c[4][4][4];
#pragma unroll
    for (int i = 0; i < 4; i++)
#pragma unroll
        for (int j = 0; j < 4; j++)
#pragma unroll
            for (int q = 0; q < 4; q++) c[i][j][q] = 0.f;

    const uint32_t aBase = sb + (uint32_t)(wm * 64 * 80) + aLoff;
    const uint32_t bBase = sb + 20480u + (uint32_t)(wn * 32 * 80) + bLoff;
#pragma unroll
    for (int ks = 0; ks < 2; ks++) {
        uint32_t afh[4][4], afl[4][4];
#pragma unroll
        for (int mi = 0; mi < 4; mi++) {
            ldsm4(afh[mi], aBase + 0u     + (uint32_t)(mi * 1280 + ks * 32));
            ldsm4(afl[mi], aBase + 10240u + (uint32_t)(mi * 1280 + ks * 32));
        }
        uint32_t bfh[2][4], bfl[2][4];
#pragma unroll
        for (int np = 0; np < 2; np++) {
            ldsm4(bfh[np], bBase + 0u     + (uint32_t)(np * 1280 + ks * 32));
            ldsm4(bfl[np], bBase + 10240u + (uint32_t)(np * 1280 + ks * 32));
        }
#pragma unroll
        for (int mi = 0; mi < 4; mi++) {
#pragma unroll
            for (int ni = 0; ni < 4; ni++) {
                const uint32_t* bh = &bfh[ni >> 1][(ni & 1) * 2];
                const uint32_t* bl = &bfl[ni >> 1][(ni & 1) * 2];
                mma_bf16(c[mi][ni], afh[mi], bh);
                mma_bf16(c[mi][ni], afh[mi], bl);
                mma_bf16(c[mi][ni], afl[mi], bh);
            }
        }
    }

    const float* maa;
    bf16 *oh, *ol;
    switch (f) {
        case 0:  maa = m_rg; oh = g_s.xrgh; ol = g_s.xrgl; break;
        case 1:  maa = m_wa; oh = g_s.xwah; ol = g_s.xwal; break;
        case 2:  maa = m_k;  oh = g_s.xkh;  ol = g_s.xkl;  break;
        default: maa = m_v;  oh = g_s.xvh;  ol = g_s.xvl;  break;
    }
    const int erow = m0 + wm * 64 + (lane >> 2);
    const int ecol = col0 + wn * 32 + (lane & 3) * 2;
#pragma unroll
    for (int mi = 0; mi < 4; mi++) {
#pragma unroll
        for (int ni = 0; ni < 4; ni++) {
            const int col = ecol + ni * 8;
            const int r0 = erow + mi * 16, r1 = r0 + 8;
            const size_t off0 = (size_t)r0 * 1024 + col;
            const size_t off1 = (size_t)r1 * 1024 + col;
            float2 mv  = *(const float2*)&maa[col];
            float2 x0  = *(const float2*)&x[off0];
            float2 x1  = *(const float2*)&x[off1];
            float2 dx0 = *(const float2*)&g_s.xx[off0];
            float2 dx1 = *(const float2*)&g_s.xx[off1];
            float v0 = x0.x + dx0.x * (mv.x + c[mi][ni][0]);
            float v1 = x0.y + dx0.y * (mv.y + c[mi][ni][1]);
            float v2 = x1.x + dx1.x * (mv.x + c[mi][ni][2]);
            float v3 = x1.y + dx1.y * (mv.y + c[mi][ni][3]);
            uint32_t h0, l0, h1, l1;
            split2(v0, v1, h0, l0);
            split2(v2, v3, h1, l1);
            *(uint32_t*)&oh[off0] = h0;
            *(uint32_t*)&ol[off0] = l0;
            *(uint32_t*)&oh[off1] = h1;
            *(uint32_t*)&ol[off1] = l1;
        }
    }
}

// ---------------------------------------------------------------------------
// gemm_down: fused LoRA down-projections (block-diagonal).
// ---------------------------------------------------------------------------
__global__ void __launch_bounds__(256, 2)
gemm_down(const float* __restrict__ tdecay, const float* __restrict__ taaaaa,
          const float* __restrict__ tmisca, const float* __restrict__ tmisck)
{
    extern __shared__ __align__(16) char sm[];
    const uint32_t sb = smem_u32(sm);

    const int tid  = threadIdx.x;
    const int lane = tid & 31;
    const int wid  = tid >> 5;
    const int wm   = wid & 1;
    const int wn   = wid >> 1;
    const int n0 = blockIdx.x * 128;
    const int m0 = blockIdx.y * 128;

    const int row = tid >> 1, half = tid & 1;
    const bf16* pAh = g_s.loraAh + (size_t)(m0 + row) * 160 + half * 16;
    const bf16* pAl = g_s.loraAl + (size_t)(m0 + row) * 160 + half * 16;
    const bf16* pBh = g_s.bigBh  + (size_t)(n0 + row) * 160 + half * 16;
    const bf16* pBl = g_s.bigBl  + (size_t)(n0 + row) * 160 + half * 16;
    const uint32_t st = (uint32_t)(row * 80 + half * 32);

    const uint32_t aLoff = (uint32_t)((lane & 15) * 80 + (lane >> 4) * 16);
    const uint32_t bLoff = (uint32_t)(((lane & 7) + ((lane >> 4) & 1) * 8) * 80
                                      + ((lane >> 3) & 1) * 16);

    float c[4][4][4];
#pragma unroll
    for (int i = 0; i < 4; i++)
#pragma unroll
        for (int j = 0; j < 4; j++)
#pragma unroll
            for (int q = 0; q < 4; q++) c[i][j][q] = 0.f;

    {
        uint32_t d = sb + st;
        cp_async16(d,             pAh); cp_async16(d + 16,         pAh + 8);
        cp_async16(d + 10240,     pAl); cp_async16(d + 10240 + 16, pAl + 8);
        cp_async16(d + 20480,     pBh); cp_async16(d + 20480 + 16, pBh + 8);
        cp_async16(d + 30720,     pBl); cp_async16(d + 30720 + 16, pBl + 8);
        CP_COMMIT();
        CP_WAIT0();
    }
    __syncthreads();

    for (int cidx = 0; cidx < 5; cidx++) {
        const uint32_t bufOff = (uint32_t)((cidx & 1) * 40960);
        const bool more = (cidx + 1 < 5);

        if (more) {
            const int ko = (cidx + 1) * 32;
            uint32_t d = sb + (uint32_t)(((cidx + 1) & 1) * 40960) + st;
            cp_async16(d,             pAh + ko); cp_async16(d + 16,         pAh + ko + 8);
            cp_async16(d + 10240,     pAl + ko); cp_async16(d + 10240 + 16, pAl + ko + 8);
            cp_async16(d + 20480,     pBh + ko); cp_async16(d + 20480 + 16, pBh + ko + 8);
            cp_async16(d + 30720,     pBl + ko); cp_async16(d + 30720 + 16, pBl + ko + 8);
            CP_COMMIT();
        }

        const uint32_t aBase = sb + bufOff + (uint32_t)(wm * 64 * 80) + aLoff;
        const uint32_t bBase = sb + bufOff + 20480u + (uint32_t)(wn * 32 * 80) + bLoff;
#pragma unroll
        for (int ks = 0; ks < 2; ks++) {
            uint32_t afh[4][4], afl[4][4];
#pragma unroll
            for (int mi = 0; mi < 4; mi++) {
                ldsm4(afh[mi], aBase + 0u     + (uint32_t)(mi * 1280 + ks * 32));
                ldsm4(afl[mi], aBase + 10240u + (uint32_t)(mi * 1280 + ks * 32));
            }
            uint32_t bfh[2][4], bfl[2][4];
#pragma unroll
            for (int np = 0; np < 2; np++) {
                ldsm4(bfh[np], bBase + 0u     + (uint32_t)(np * 1280 + ks * 32));
                ldsm4(bfl[np], bBase + 10240u + (uint32_t)(np * 1280 + ks * 32));
            }
#pragma unroll
            for (int mi = 0; mi < 4; mi++) {
#pragma unroll
                for (int ni = 0; ni < 4; ni++) {
                    const uint32_t* bh = &bfh[ni >> 1][(ni & 1) * 2];
                    const uint32_t* bl = &bfl[ni >> 1][(ni & 1) * 2];
                    mma_bf16(c[mi][ni], afh[mi], bh);
                    mma_bf16(c[mi][ni], afh[mi], bl);
                    mma_bf16(c[mi][ni], afl[mi], bh);
                }
            }
        }

        if (more) CP_WAIT0();
        __syncthreads();
    }

    const int blk = n0 >> 10;
    float* outp; const float* ev; int mode;
    switch (blk) {
        case 0:  outp = g_s.w;    ev = tdecay; mode = 4; break;
        case 1:  outp = g_s.asig; ev = taaaaa; mode = 3; break;
        case 2:  outp = g_s.ma;   ev = tmisca; mode = 3; break;
        case 3:  outp = g_s.kk;   ev = 0;      mode = 5; break;
        default: outp = g_s.mk2;  ev = tmisck; mode = 3; break;
    }
    const int erow = m0 + wm * 64 + (lane >> 2);
    const int ecol = (n0 & 1023) + wn * 32 + (lane & 3) * 2;
#pragma unroll
    for (int mi = 0; mi < 4; mi++) {
#pragma unroll
        for (int ni = 0; ni < 4; ni++) {
            const int col = ecol + ni * 8;
            const int r0 = erow + mi * 16, r1 = r0 + 8;
            float v0 = c[mi][ni][0], v1 = c[mi][ni][1];
            float v2 = c[mi][ni][2], v3 = c[mi][ni][3];
            if (mode == 4) {
                float e0 = ev[col], e1 = ev[col + 1];
                v0 = -log1pf(expf(-(e0 + v0))) - 0.5f;
                v1 = -log1pf(expf(-(e1 + v1))) - 0.5f;
                v2 = -log1pf(expf(-(e0 + v2))) - 0.5f;
                v3 = -log1pf(expf(-(e1 + v3))) - 0.5f;
            } else if (mode == 3) {
                float e0 = ev[col], e1 = ev[col + 1];
                v0 = 1.f / (1.f + expf(-(e0 + v0)));
                v1 = 1.f / (1.f + expf(-(e1 + v1)));
                v2 = 1.f / (1.f + expf(-(e0 + v2)));
                v3 = 1.f / (1.f + expf(-(e1 + v3)));
            } else {
                float2 k0 = *(const float2*)&g_s.k[(size_t)r0 * 1024 + col];
                float2 k1 = *(const float2*)&g_s.k[(size_t)r1 * 1024 + col];
                v0 += k0.x; v1 += k0.y; v2 += k1.x; v3 += k1.y;
            }
            *(float2*)&outp[(size_t)r0 * 1024 + col] = make_float2(v0, v1);
            *(float2*)&outp[(size_t)r1 * 1024 + col] = make_float2(v2, v3);
        }
    }
}

// ---------------------------------------------------------------------------
// up-projection core (CTA 32x64, cp.async dbl-buffered, chunk 32)
// ---------------------------------------------------------------------------
#define UP64_SMEM 30720

__device__ __forceinline__ void up64_body(
    const bf16* __restrict__ Ah, const bf16* __restrict__ Al,
    const bf16* __restrict__ Bh, const bf16* __restrict__ Bl,
    int m0, int n0, int tanhN, int maxcol,
    float* __restrict__ Cm, int cstride,
    bf16* __restrict__ oh, bf16* __restrict__ ol, int ostride, int ocol,
    char* sm)
{
    constexpr int B_BYTES = 64 * 80;          // 5120
    constexpr int OFF_AL = 2560;
    constexpr int OFF_BH = 5120;
    constexpr int BUF = 5120 + 2 * B_BYTES;   // 15360

    const uint32_t sb = smem_u32(sm);
    const int tid  = threadIdx.x;
    const int lane = tid & 31;
    const int wid  = tid >> 5;
    const int wm   = wid & 1;
    const int wn   = wid >> 1;

    const int arow = (tid & 127) >> 2, aq2 = tid & 3;
    const bf16* pAh = Ah + (size_t)(m0 + arow) * 1024 + aq2 * 8;
    const bf16* pAl = Al + (size_t)(m0 + arow) * 1024 + aq2 * 8;
    const uint32_t stA = (uint32_t)(arow * 80 + aq2 * 16);
    const int brow = tid >> 2;
    const bf16* pBh = Bh + (size_t)(n0 + brow) * 1024 + aq2 * 8;
    const bf16* pBl = Bl + (size_t)(n0 + brow) * 1024 + aq2 * 8;
    const uint32_t stB = (uint32_t)(brow * 80 + aq2 * 16);
    const bool doA = (tid < 128);

    const uint32_t aLoff = (uint32_t)((lane & 15) * 80 + (lane >> 4) * 16);
    const uint32_t bLoff = (uint32_t)(((lane & 7) + ((lane >> 4) & 1) * 8) * 80
                                      + ((lane >> 3) & 1) * 16);

    float c[2][4];
#pragma unroll
    for (int j = 0; j < 2; j++)
#pragma unroll
        for (int q = 0; q < 4; q++) c[j][q] = 0.f;

    {
        if (doA) {
            cp_async16(sb + stA, pAh);
            cp_async16(sb + OFF_AL + stA, pAl);
        }
        cp_async16(sb + OFF_BH + stB, pBh);
        cp_async16(sb + OFF_BH + B_BYTES + stB, pBl);
        CP_COMMIT();
        CP_WAIT0();
    }
    __syncthreads();

    for (int cidx = 0; cidx < 32; cidx++) {
        const uint32_t bufOff = (uint32_t)((cidx & 1) * BUF);
        const bool more = (cidx + 1 < 32);

        if (more) {
            const int ko = (cidx + 1) * 32;
            uint32_t d = sb + (uint32_t)(((cidx + 1) & 1) * BUF);
            if (doA) {
                cp_async16(d + stA, pAh + ko);
                cp_async16(d + OFF_AL + stA, pAl + ko);
            }
            cp_async16(d + OFF_BH + stB, pBh + ko);
            cp_async16(d + OFF_BH + B_BYTES + stB, pBl + ko);
            CP_COMMIT();
        }

        const uint32_t aBase = sb + bufOff + (uint32_t)(wm * 16 * 80) + aLoff;
#pragma unroll
        for (int ks = 0; ks < 2; ks++) {
            uint32_t afh[4], afl[4];
            ldsm4(afh, aBase + (uint32_t)(ks * 32));
            ldsm4(afl, aBase + OFF_AL + (uint32_t)(ks * 32));
            uint32_t bfh[4], bfl[4];
            const uint32_t bBase = sb + bufOff + OFF_BH
                                 + (uint32_t)(wn * 16 * 80) + bLoff
                                 + (uint32_t)(ks * 32);
            ldsm4(bfh, bBase);
            ldsm4(bfl, bBase + (uint32_t)B_BYTES);
#pragma unroll
            for (int ni = 0; ni < 2; ni++) {
                const uint32_t* bhp = &bfh[ni * 2];
                const uint32_t* blp = &bfl[ni * 2];
                mma_bf16(c[ni], afh, bhp);
                mma_bf16(c[ni], afh, blp);
                mma_bf16(c[ni], afl, bhp);
            }
        }

        if (more) CP_WAIT0();
        __syncthreads();
    }

    const int r0 = m0 + wm * 16 + (lane >> 2);
    const int r1 = r0 + 8;
#pragma unroll
    for (int ni = 0; ni < 2; ni++) {
        const int gcol = n0 + wn * 16 + ni * 8 + (lane & 3) * 2;
        float v0 = c[ni][0], v1 = c[ni][1];
        float v2 = c[ni][2], v3 = c[ni][3];
        if (gcol < tanhN) {
            v0 = tanhf(v0); v1 = tanhf(v1);
            v2 = tanhf(v2); v3 = tanhf(v3);
        }
        if (gcol < maxcol) {
            if (Cm) {
                *(float2*)&Cm[(size_t)r0 * cstride + gcol] = make_float2(v0, v1);
                *(float2*)&Cm[(size_t)r1 * cstride + gcol] = make_float2(v2, v3);
            }
            if (oh) {
                uint32_t h0, l0, h1, l1;
                split2(v0, v1, h0, l0);
                split2(v2, v3, h1, l1);
                *(uint32_t*)&oh[(size_t)r0 * ostride + ocol + gcol] = h0;
                *(uint32_t*)&ol[(size_t)r0 * ostride + ocol + gcol] = l0;
                *(uint32_t*)&oh[(size_t)r1 * ostride + ocol + gcol] = h1;
                *(uint32_t*)&ol[(size_t)r1 * ostride + ocol + gcol] = l1;
            }
        }
    }
}

// mixin up-projection: writes bf16 hi/lo (mixinh/mixinl, stride 128)
__global__ void __launch_bounds__(256)
gemm_up_mix()
{
    extern __shared__ __align__(16) char sm[];
    up64_body(g_s.xmixh, g_s.xmixl, g_s.mw1Th, g_s.mw1Tl,
              blockIdx.x * 32, blockIdx.y * 64, 128, 128,
              0, 0, g_s.mixinh, g_s.mixinl, 128, 0, sm);
}

// batched post-mix up-projections: y 0-1 gate1, 2-3 lora_wa, 4 lora_k
__global__ void __launch_bounds__(256)
gemm_up_batch()
{
    extern __shared__ __align__(16) char sm[];
    const int y = blockIdx.y;
    const int m0 = blockIdx.x * 32;
    if (y < 2) {
        up64_body(g_s.xrgh, g_s.xrgl, g_s.gw1Th, g_s.gw1Tl,
                  m0, y * 64, 128, 128,
                  0, 0, g_s.g1h, g_s.g1l, 128, 0, sm);
    } else if (y < 4) {
        up64_body(g_s.xwah, g_s.xwal, g_s.waTh, g_s.waTl,
                  m0, (y - 2) * 64, 64, 128,
                  0, 0, g_s.loraAh, g_s.loraAl, 160, 0, sm);
    } else {
        up64_body(g_s.xkh, g_s.xkl, g_s.kTh, g_s.kTl,
                  m0, 0, 16, 32,
                  0, 0, g_s.loraAh, g_s.loraAl, 160, 128, sm);
    }
}

// ---------------------------------------------------------------------------
// conv4: 4 weight matrices fp32 -> bf16 hi/lo in one launch
// ---------------------------------------------------------------------------
__global__ void __launch_bounds__(256)
conv4(const float* __restrict__ w0, const float* __restrict__ w1,
      const float* __restrict__ w2, const float* __restrict__ w3)
{
    const int wq = blockIdx.x >> 10;
    const int i  = (blockIdx.x & 1023) * 256 + threadIdx.x;
    const float* src; bf16 *dh, *dl;
    switch (wq) {
        case 0:  src = w0; dh = g_s.wrh; dl = g_s.wrl; break;
        case 1:  src = w1; dh = g_s.wkh; dl = g_s.wkl; break;
        case 2:  src = w2; dh = g_s.wvh; dl = g_s.wvl; break;
        default: src = w3; dh = g_s.woh; dl = g_s.wol; break;
    }
    uint2 hh, ll;
    split4(((const float4*)src)[i], hh, ll);
    ((uint2*)dh)[i] = hh;
    ((uint2*)dl)[i] = ll;
}

// ---------------------------------------------------------------------------
// transconv / packT / pack_bigB / pack_mix
// ---------------------------------------------------------------------------
__global__ void __launch_bounds__(256)
transconv_kernel(const float* __restrict__ src, bf16* __restrict__ dh,
                 bf16* __restrict__ dl)
{
    __shared__ float tile[32][33];
    int bx = blockIdx.x;
    int by = blockIdx.y;
    int tx = threadIdx.x & 31, ty = threadIdx.x >> 5;
#pragma unroll
    for (int i = 0; i < 4; i++)
        tile[ty + i * 8][tx] = src[(size_t)(by * 32 + ty + i * 8) * 1024 + bx * 32 + tx];
    __syncthreads();
#pragma unroll
    for (int i = 0; i < 4; i++) {
        float v = tile[tx][ty + i * 8];
        bf16 hv, lv; splitf(v, hv, lv);
        size_t di = (size_t)(bx * 32 + ty + i * 8) * 128 + by * 32 + tx;
        dh[di] = hv; dl[di] = lv;
    }
}

__global__ void __launch_bounds__(256)
packT_w1(const float* __restrict__ src, bf16* __restrict__ dh,
         bf16* __restrict__ dl)
{
    int idx = blockIdx.x * 256 + threadIdx.x;
    int cth = idx >> 10, r = idx & 1023;
    bf16 hv, lv; splitf(src[(size_t)r * 128 + cth], hv, lv);
    dh[idx] = hv; dl[idx] = lv;
}

// pack_mix: blocks 0-511 = maa_w1 transpose; 512-1023 = W2 block-transpose
__global__ void __launch_bounds__(256)
pack_mix(const float* __restrict__ w1, const float* __restrict__ w2)
{
    const int b = blockIdx.x;
    if (b < 512) {
        int idx = b * 256 + threadIdx.x;          // 128*1024
        int cth = idx >> 10, r = idx & 1023;
        bf16 hv, lv; splitf(w1[(size_t)r * 128 + cth], hv, lv);
        g_s.mw1Th[idx] = hv; g_s.mw1Tl[idx] = lv;
    } else {
        int idx = (b - 512) * 256 + threadIdx.x;  // 4096*32
        int n = idx >> 5, kq = idx & 31;
        int f = n >> 10, nloc = n & 1023;
        bf16 hv, lv;
        splitf(w2[(size_t)(f * 32 + kq) * 1024 + nloc], hv, lv);
        g_s.w2Th[idx] = hv; g_s.w2Tl[idx] = lv;
    }
}

__global__ void __launch_bounds__(256)
packT_wa(const float* __restrict__ dw1, const float* __restrict__ aw1,
         const float* __restrict__ maw1)
{
    int idx = blockIdx.x * 256 + threadIdx.x;
    int cth = idx >> 10, r = idx & 1023;
    float v = 0.f;
    if (cth < 64)      v = dw1[r * 64 + cth];
    else if (cth < 80) v = aw1[r * 16 + (cth - 64)];
    else if (cth < 96) v = maw1[r * 16 + (cth - 80)];
    bf16 hv, lv; splitf(v, hv, lv);
    g_s.waTh[idx] = hv; g_s.waTl[idx] = lv;
}
__global__ void __launch_bounds__(256)
packT_k(const float* __restrict__ kw1, const float* __restrict__ mkw1)
{
    int idx = blockIdx.x * 256 + threadIdx.x;   // 64*1024
    int cth = idx >> 10, r = idx & 1023;
    float v = 0.f;
    if (cth < 16)      v = kw1[r * 16 + cth];
    else if (cth < 32) v = mkw1[r * 16 + (cth - 16)];
    bf16 hv, lv; splitf(v, hv, lv);
    g_s.kTh[idx] = hv; g_s.kTl[idx] = lv;
}

__global__ void __launch_bounds__(256)
pack_bigB(const float* __restrict__ dw2, const float* __restrict__ aw2,
          const float* __restrict__ maw2, const float* __restrict__ kw2,
          const float* __restrict__ mkw2)
{
    int idx = blockIdx.x * 256 + threadIdx.x;
    int n = idx / 160, kq = idx - (idx / 160) * 160;
    int blk = n >> 10, nloc = n & 1023;
    float v = 0.f;
    switch (blk) {
        case 0: if (kq < 64)               v = dw2 [(size_t)kq * 1024 + nloc]; break;
        case 1: if (kq >= 64 && kq < 80)   v = aw2 [(size_t)(kq - 64) * 1024 + nloc]; break;
        case 2: if (kq >= 80 && kq < 96)   v = maw2[(size_t)(kq - 80) * 1024 + nloc]; break;
        case 3: if (kq >= 128 && kq < 144) v = kw2 [(size_t)(kq - 128) * 1024 + nloc]; break;
        default:if (kq >= 144)             v = mkw2[(size_t)(kq - 144) * 1024 + nloc]; break;
    }
    bf16 hv, lv; splitf(v, hv, lv);
    g_s.bigBh[idx] = hv; g_s.bigBl[idx] = lv;
}

// ---------------------------------------------------------------------------
// ew0
// ---------------------------------------------------------------------------
__global__ void __launch_bounds__(256)
ew0_kernel(const float* __restrict__ x, const float* __restrict__ maa_x)
{
    size_t i4  = (size_t)blockIdx.x * 256 + threadIdx.x;
    size_t idx = i4 * 4;
    int c    = (int)(idx & (CC - 1));
    int nrow = (int)(idx >> 10);
    float4 xv = *(const float4*)&x[idx];
    float4 xp = make_float4(0.f, 0.f, 0.f, 0.f);
    if (nrow & (TT - 1))
        xp = *(const float4*)&x[idx - CC];
    float4 mv = *(const float4*)&maa_x[c];
    float4 d, xm;
    d.x = xp.x - xv.x;  xm.x = xv.x + d.x * mv.x;
    d.y = xp.y - xv.y;  xm.y = xv.y + d.y * mv.y;
    d.z = xp.z - xv.z;  xm.z = xv.z + d.z * mv.z;
    d.w = xp.w - xv.w;  xm.w = xv.w + d.w * mv.w;
    *(float4*)&g_s.xx[idx] = d;
    uint2 h, l;
    split4(xm, h, l);
    *(uint2*)&g_s.xmixh[idx] = h;
    *(uint2*)&g_s.xmixl[idx] = l;
}

// ---------------------------------------------------------------------------
// combine
// ---------------------------------------------------------------------------
__global__ void __launch_bounds__(256)
combine_kernel()
{
    int n   = blockIdx.x;
    int tid = threadIdx.x;
    size_t off = (size_t)n * CC + tid * 4;

    float4 kkv = *(float4*)&g_s.kk[off];
    float ss = kkv.x*kkv.x + kkv.y*kkv.y + kkv.z*kkv.z + kkv.w*kkv.w;
#pragma unroll
    for (int o = 8; o; o >>= 1) ss += __shfl_xor_sync(0xffffffffu, ss, o, 16);
    float inv = 1.f / fmaxf(sqrtf(ss), 1e-12f);

    float4 kq = *(float4*)&g_s.k[off];
    float4 aq = *(float4*)&g_s.asig[off];
    float4 mq = *(float4*)&g_s.ma[off];
    float4 wq = *(float4*)&g_s.w[off];
    float4 mk = *(float4*)&g_s.mk2[off];
    float4 kfv, ddv, avv, bvv;
#define CMB(X) { float fac = mq.X + aq.X * (1.f - mq.X); \
    float ee = expf(fminf(wq.X * mk.X, 0.f)); \
    kfv.X = kq.X * fac * ee; \
    ddv.X = expf(wq.X); \
    float kn = kkv.X * inv; \
    avv.X = -kn; bvv.X = kn * aq.X; }
    CMB(x) CMB(y) CMB(z) CMB(w)
#undef CMB
    *(float4*)&g_s.kf[off] = kfv;
    *(float4*)&g_s.dd[off] = ddv;
    *(float4*)&g_s.av[off] = avv;
    *(float4*)&g_s.bv[off] = bvv;
}

// ---------------------------------------------------------------------------
// WKV-7 scan: cp.async 3-deep pipeline
// ---------------------------------------------------------------------------
__global__ void __launch_bounds__(256)
wkv_kernel()
{
    const int blk = blockIdx.x;
    const int b = blk >> 4;
    const int h = blk & 15;
    const int tid = threadIdx.x;
    const int i  = tid >> 2;
    const int jq = tid & 3;

    __shared__ __align__(16) float sb[4][6][64];
    const size_t rowbase = ((size_t)b * TT) * CC + h * NN;

    const float* gsrc = 0;
    uint32_t sdst[4];
    if (tid < 96) {
        int larr = tid >> 4, lq = tid & 15;
        const float* srcs[6] = { g_s.r, g_s.dd, g_s.kf, g_s.av, g_s.bv, g_s.v };
        gsrc = srcs[larr] + rowbase + lq * 4;
#pragma unroll
        for (int q = 0; q < 4; q++) sdst[q] = smem_u32(&sb[q][larr][lq * 4]);
    }

#pragma unroll
    for (int pre = 0; pre < 3; pre++) {
        if (tid < 96) cp_async16(sdst[pre], gsrc + (size_t)pre * CC);
        CP_COMMIT();
    }

    unsigned long long S2[8];
#pragma unroll
    for (int u = 0; u < 8; u++) S2[u] = 0ull;

    float* yout = g_s.y + rowbase + i;

    for (int t = 0; t < TT; t++) {
        CP_WAIT2();
        __syncthreads();
        const int p = t & 3;

        const ulonglong2* r2p = (const ulonglong2*)(sb[p][0] + jq * 16);
        const ulonglong2* d2p = (const ulonglong2*)(sb[p][1] + jq * 16);
        const ulonglong2* k2p = (const ulonglong2*)(sb[p][2] + jq * 16);
        const ulonglong2* a2p = (const ulonglong2*)(sb[p][3] + jq * 16);
        const ulonglong2* b2p = (const ulonglong2*)(sb[p][4] + jq * 16);
        const float vi = sb[p][5][i];

        ulonglong2 Rv[4], Dv[4], Kv[4], Av[4], Bv[4];
#pragma unroll
        for (int u = 0; u < 4; u++) {
            Rv[u] = r2p[u]; Dv[u] = d2p[u]; Kv[u] = k2p[u];
            Av[u] = a2p[u]; Bv[u] = b2p[u];
        }

        if (tid < 96 && t + 3 < TT)
            cp_async16(sdst[(t + 3) & 3], gsrc + (size_t)(t + 3) * CC);
        CP_COMMIT();

        unsigned long long sa0 = 0ull, sa1 = 0ull, pp0 = 0ull, pp1 = 0ull;
        unsigned long long br0 = 0ull, br1 = 0ull, kr0 = 0ull, kr1 = 0ull;
#pragma unroll
        for (int u = 0; u < 4; u++) {
            unsigned long long drx = mul2(Dv[u].x, Rv[u].x);
            unsigned long long dry = mul2(Dv[u].y, Rv[u].y);
            fma2(sa0, S2[2*u],   Av[u].x);
            fma2(sa1, S2[2*u+1], Av[u].y);
            fma2(pp0, S2[2*u],   drx);
            fma2(pp1, S2[2*u+1], dry);
            fma2(br0, Bv[u].x, Rv[u].x);
            fma2(br1, Bv[u].y, Rv[u].y);
            fma2(kr0, Kv[u].x, Rv[u].x);
            fma2(kr1, Kv[u].y, Rv[u].y);
        }
        float sa = hadd4(sa0, sa1);
        float pp = hadd4(pp0, pp1);
        float br = hadd4(br0, br1);
        float kr = hadd4(kr0, kr1);
        sa += __shfl_xor_sync(0xffffffffu, sa, 1, 4);
        pp += __shfl_xor_sync(0xffffffffu, pp, 1, 4);
        br += __shfl_xor_sync(0xffffffffu, br, 1, 4);
        kr += __shfl_xor_sync(0xffffffffu, kr, 1, 4);
        sa += __shfl_xor_sync(0xffffffffu, sa, 2, 4);
        pp += __shfl_xor_sync(0xffffffffu, pp, 2, 4);
        br += __shfl_xor_sync(0xffffffffu, br, 2, 4);
        kr += __shfl_xor_sync(0xffffffffu, kr, 2, 4);

        if (jq == 0) yout[(size_t)t * CC] = pp + sa * br + vi * kr;

        const unsigned long long sa2 = dup2(sa);
        const unsigned long long v2  = dup2(vi);
#pragma unroll
        for (int u = 0; u < 4; u++) {
            S2[2*u]   = fma2g(S2[2*u],   Dv[u].x,
                              fma2g(sa2, Bv[u].x, mul2(v2, Kv[u].x)));
            S2[2*u+1] = fma2g(S2[2*u+1], Dv[u].y,
                              fma2g(sa2, Bv[u].y, mul2(v2, Kv[u].y)));
        }
    }
}

// ---------------------------------------------------------------------------
// post: GroupNorm + bonus + gate -> z (bf16 hi/lo)
// ---------------------------------------------------------------------------
__global__ void __launch_bounds__(256)
post_kernel(const float* __restrict__ faaaa,
            const float* __restrict__ lnw, const float* __restrict__ lnb)
{
    int n   = blockIdx.x;
    int tid = threadIdx.x;
    int c   = tid * 4;
    size_t off = (size_t)n * CC + c;

    float4 yv = *(float4*)&g_s.y [off];
    float4 rv = *(float4*)&g_s.r [off];
    float4 kv = *(float4*)&g_s.kf[off];
    float4 vv = *(float4*)&g_s.v [off];
    float4 gv = *(float4*)&g_s.g [off];
    float4 fv = *(const float4*)&faaaa[c];

    float s  = yv.x + yv.y + yv.z + yv.w;
    float s2 = yv.x*yv.x + yv.y*yv.y + yv.z*yv.z + yv.w*yv.w;
    float dk = rv.x*kv.x*fv.x + rv.y*kv.y*fv.y + rv.z*kv.z*fv.z + rv.w*kv.w*fv.w;
#pragma unroll
    for (int o = 8; o; o >>= 1) {
        s  += __shfl_xor_sync(0xffffffffu, s,  o, 16);
        s2 += __shfl_xor_sync(0xffffffffu, s2, o, 16);
        dk += __shfl_xor_sync(0xffffffffu, dk, o, 16);
    }
    float mean = s  * (1.f / 64.f);
    float var  = s2 * (1.f / 64.f) - mean * mean;
    float rs   = rsqrtf(var + 64e-5f);

    float4 lw = *(const float4*)&lnw[c];
    float4 lb = *(const float4*)&lnb[c];
    float4 z;
    z.x = (((yv.x - mean) * rs) * lw.x + lb.x + dk * vv.x) * gv.x;
    z.y = (((yv.y - mean) * rs) * lw.y + lb.y + dk * vv.y) * gv.y;
    z.z = (((yv.z - mean) * rs) * lw.z + lb.z + dk * vv.z) * gv.z;
    z.w = (((yv.w - mean) * rs) * lw.w + lb.w + dk * vv.w) * gv.w;
    uint2 h, l;
    split4(z, h, l);
    *(uint2*)&g_s.zh[off] = h;
    *(uint2*)&g_s.zl[off] = l;
}

// ---------------------------------------------------------------------------
// Host orchestration
// ---------------------------------------------------------------------------
static void gmma(const bf16* Ah, const bf16* Al, const bf16* Bh,
                 const bf16* Bl, float* Cp, int K)
{
    dim3 grid(8, MM / 128);
    gemm_mma2<<<grid, 256, MMA_SMEM>>>(Ah, Al, Bh, Bl, Cp, K);
}

extern "C" void kernel_launch(void* const* d_in, const int* in_sizes, int n_in,
                              void* d_out, int out_size)
{
    const float* x       = (const float*)d_in[0];
    const float* maa_x   = (const float*)d_in[1];
    const float* maa_rg  = (const float*)d_in[2];
    const float* maa_wa  = (const float*)d_in[3];
    const float* maa_k   = (const float*)d_in[4];
    const float* maa_v   = (const float*)d_in[5];
    const float* maa_w1  = (const float*)d_in[6];
    const float* maa_w2  = (const float*)d_in[7];
    const float* tdecay  = (const float*)d_in[8];
    const float* dw1     = (const float*)d_in[9];
    const float* dw2     = (const float*)d_in[10];
    const float* faaaa   = (const float*)d_in[11];
    const float* taaaaa  = (const float*)d_in[12];
    const float* aw1     = (const float*)d_in[13];
    const float* aw2     = (const float*)d_in[14];
    const float* kw1     = (const float*)d_in[15];
    const float* kw2     = (const float*)d_in[16];
    const float* gw1     = (const float*)d_in[17];
    const float* gw2     = (const float*)d_in[18];
    const float* maw1    = (const float*)d_in[19];
    const float* maw2    = (const float*)d_in[20];
    const float* tmisca  = (const float*)d_in[21];
    const float* mkw1    = (const float*)d_in[22];
    const float* mkw2    = (const float*)d_in[23];
    const float* tmisck  = (const float*)d_in[24];
    const float* wr      = (const float*)d_in[25];
    const float* wk      = (const float*)d_in[26];
    const float* wv      = (const float*)d_in[27];
    const float* wo      = (const float*)d_in[28];
    const float* lnw     = (const float*)d_in[29];
    const float* lnb     = (const float*)d_in[30];
    float* out = (float*)d_out;
    (void)in_sizes; (void)n_in; (void)out_size;

    Scratch* S = nullptr;
    cudaGetSymbolAddress((void**)&S, g_s);
    cudaFuncSetAttribute(gemm_mma2, cudaFuncAttributeMaxDynamicSharedMemorySize,
                         MMA_SMEM);
    cudaFuncSetAttribute(gemm_down, cudaFuncAttributeMaxDynamicSharedMemorySize,
                         MMA_SMEM);
    cudaFuncSetAttribute(gemm_mix_mma,
                         cudaFuncAttributeMaxDynamicSharedMemorySize, MIXMMA_SMEM);
    cudaFuncSetAttribute(gemm_up_mix,
                         cudaFuncAttributeMaxDynamicSharedMemorySize, UP64_SMEM);
    cudaFuncSetAttribute(gemm_up_batch,
                         cudaFuncAttributeMaxDynamicSharedMemorySize, UP64_SMEM);

    // 1-4: ncu captures the 4th launch -> gemm_mix_mma
    ew0_kernel<<<(MM * CC / 4) / 256, 256>>>(x, maa_x);                  // 1
    pack_mix<<<1024, 256>>>(maa_w1, maa_w2);                             // 2
    gemm_up_mix<<<dim3(128, 2), 256, UP64_SMEM>>>();                     // 3
    gemm_mix_mma<<<dim3(32, 32), 256, MIXMMA_SMEM>>>(x,                  // 4
        maa_rg, maa_wa, maa_k, maa_v);

    // weight conversions / packs
    conv4<<<4096, 256>>>(wr, wk, wv, wo);
    packT_w1<<<512, 256>>>(gw1, S->gw1Th, S->gw1Tl);
    packT_wa<<<512, 256>>>(dw1, aw1, maw1);
    packT_k<<<256, 256>>>(kw1, mkw1);
    transconv_kernel<<<dim3(32, 4), 256>>>(gw2, S->gw2Th, S->gw2Tl);
    pack_bigB<<<(5120 * 160) / 256, 256>>>(dw2, aw2, maw2, kw2, mkw2);

    // big projections
    gmma(S->xrgh, S->xrgl, S->wrh, S->wrl, S->r, 1024);
    gmma(S->xkh,  S->xkl,  S->wkh, S->wkl, S->k, 1024);
    gmma(S->xvh,  S->xvl,  S->wvh, S->wvl, S->v, 1024);

    // batched up-projections (gate1 + lora_wa + lora_k)
    gemm_up_batch<<<dim3(128, 5), 256, UP64_SMEM>>>();

    // gate down-projection
    gmma(S->g1h, S->g1l, S->gw2Th, S->gw2Tl, S->g, 128);

    // fused block-diagonal LoRA down-projection
    gemm_down<<<dim3(40, 32), 256, MMA_SMEM>>>(tdecay, taaaaa, tmisca, tmisck);

    // combine + scan + post + output
    combine_kernel<<<MM, 256>>>();
    wkv_kernel<<<BB * HH, 256>>>();
    post_kernel<<<MM, 256>>>(faaaa, lnw, lnb);
    gmma(S->zh, S->zl, S->woh, S->wol, out, 1024);
}